// round 1
// baseline (speedup 1.0000x reference)
#include <cuda_runtime.h>
#include <cuda_bf16.h>
#include <math.h>

// ---------------------------------------------------------------------------
// ToyMoE: conv stack (5x conv3x3+relu+maxpool2) -> noisy_top_k gating (eval)
//         -> sparse top-2 expert MLPs -> softmax -> gated combine + aux loss
// B=256, D=2048, HID=4096, O=1024, E=16, K(topk)=2
// ---------------------------------------------------------------------------

#define BATCH 256
#define DFEAT 2048
#define HID 4096
#define OUTD 1024
#define NEXP 16
#define NPAIR (BATCH * 2)

// ------------------------- scratch (device globals) ------------------------
__device__ float g_conv[(size_t)256 * 128 * 64 * 64];   // 512 MB: conv outputs (pre-pool)
__device__ float g_pool[(size_t)256 * 128 * 32 * 32];   // 128 MB: pooled outputs / feats
__device__ float g_logits[BATCH * NEXP];
__device__ float g_gates[BATCH * NEXP];
__device__ int   g_pairE[NPAIR];
__device__ float g_pairG[NPAIR];
__device__ int   g_perm[NPAIR];
__device__ int   g_cnt[NEXP];
__device__ int   g_off[NEXP];
__device__ float g_h[(size_t)NPAIR * HID];              // 8 MB
__device__ float g_o[(size_t)NPAIR * OUTD];             // 2 MB

// ------------------------- conv3x3 + bias + relu ---------------------------
// Implicit GEMM: M = B*H*W (conv output positions), N = CO, K = CI*9.
// 128x128 tile, BK = 36 (4 input channels x 9 taps), 8x8 per-thread tile.
template <int CI, int H, int W, int CO>
__global__ __launch_bounds__(256) void conv3x3_relu_kernel(
    const float* __restrict__ in, const float* __restrict__ wt,
    const float* __restrict__ bias, float* __restrict__ out)
{
    constexpr int BM = 128, BN = 128, CIB = 4, BK = CIB * 9;
    constexpr int HW = H * W;

    __shared__ __align__(16) float As[BK][BM + 4];
    __shared__ __align__(16) float Bs[BK][BN + 4];

    const int t = threadIdx.x;
    const int m0 = blockIdx.x * BM;
    const int n0 = blockIdx.y * BN;
    const int tx = t & 15;   // spatial group (m)
    const int ty = t >> 4;   // channel group (n)

    float acc[8][8];
#pragma unroll
    for (int i = 0; i < 8; i++)
#pragma unroll
        for (int j = 0; j < 8; j++) acc[i][j] = 0.f;

    for (int cb = 0; cb < CI; cb += CIB) {
        // ---- load A tile (im2col on the fly): BK x BM = 4608 elems ----
#pragma unroll
        for (int j = 0; j < 18; j++) {
            int e = j * 256 + t;
            int k = e >> 7;       // 0..35
            int p = e & 127;      // 0..127
            int ci = cb + k / 9;
            int rc = k % 9;
            int s = m0 + p;
            int b = s / HW;
            int r = s % HW;
            int y = r / W, x = r % W;
            int iy = y + rc / 3 - 1;
            int ix = x + rc % 3 - 1;
            float v = 0.f;
            if (ci < CI && iy >= 0 && iy < H && ix >= 0 && ix < W)
                v = in[((size_t)(b * CI + ci) * H + iy) * W + ix];
            As[k][p] = v;
        }
        // ---- load B tile (weights): BK x BN ----
        {
            int n = t >> 1;             // 0..127
            int kbase = (t & 1) * 18;   // 0 or 18
            int co = n0 + n;
            const float* wp = wt + ((size_t)co * CI + cb) * 9;
#pragma unroll
            for (int j = 0; j < 18; j++) {
                int k = kbase + j;
                int ci = cb + k / 9;
                Bs[k][n] = (ci < CI) ? wp[k] : 0.f;
            }
        }
        __syncthreads();

#pragma unroll 4
        for (int kk = 0; kk < BK; kk++) {
            float a[8], bb[8];
            *(float4*)&a[0]  = *(const float4*)&As[kk][tx * 8];
            *(float4*)&a[4]  = *(const float4*)&As[kk][tx * 8 + 4];
            *(float4*)&bb[0] = *(const float4*)&Bs[kk][ty * 8];
            *(float4*)&bb[4] = *(const float4*)&Bs[kk][ty * 8 + 4];
#pragma unroll
            for (int i = 0; i < 8; i++)
#pragma unroll
                for (int j = 0; j < 8; j++) acc[i][j] += a[i] * bb[j];
        }
        __syncthreads();
    }

    // epilogue: bias + relu, scatter to NCHW
#pragma unroll
    for (int i = 0; i < 8; i++) {
        int m = m0 + tx * 8 + i;
        int b = m / HW;
        int r = m % HW;
        int y = r / W, x = r % W;
        size_t obase = (size_t)b * CO * HW + (size_t)y * W + x;
#pragma unroll
        for (int j = 0; j < 8; j++) {
            int co = n0 + ty * 8 + j;
            float v = acc[i][j] + bias[co];
            out[obase + (size_t)co * HW] = v > 0.f ? v : 0.f;
        }
    }
}

// ------------------------------ maxpool 2x2 --------------------------------
__global__ void maxpool2_kernel(const float* __restrict__ in,
                                float* __restrict__ out, int C, int H, int n)
{
    int Ho = H / 2;
    for (int i = blockIdx.x * blockDim.x + threadIdx.x; i < n;
         i += gridDim.x * blockDim.x) {
        int x = i % Ho;
        int y = (i / Ho) % Ho;
        int c = (i / (Ho * Ho)) % C;
        int b = i / (Ho * Ho * C);
        const float* p = in + ((size_t)(b * C + c) * H + 2 * y) * H + 2 * x;
        float v = fmaxf(fmaxf(p[0], p[1]), fmaxf(p[H], p[H + 1]));
        out[i] = v;
    }
}

// ----------------------------- gate logits ---------------------------------
__global__ void gate_logits_kernel(const float* __restrict__ feats,
                                   const float* __restrict__ wg)
{
    int t = blockIdx.x * blockDim.x + threadIdx.x;
    if (t >= BATCH * NEXP) return;
    int b = t >> 4, e = t & 15;
    const float* f = feats + (size_t)b * DFEAT;
    float s = 0.f;
    for (int d = 0; d < DFEAT; d++) s += f[d] * wg[d * NEXP + e];
    g_logits[t] = s;
}

// --------------------------- top-2 + gate softmax --------------------------
__global__ void topk_kernel()
{
    int b = threadIdx.x;
    if (b >= BATCH) return;
    float l[NEXP];
#pragma unroll
    for (int e = 0; e < NEXP; e++) l[e] = g_logits[b * NEXP + e];
    float b1v = -INFINITY, b2v = -INFINITY;
    int b1i = 0, b2i = 0;
#pragma unroll
    for (int e = 0; e < NEXP; e++) {
        float v = l[e];
        if (v > b1v) { b2v = b1v; b2i = b1i; b1v = v; b1i = e; }
        else if (v > b2v) { b2v = v; b2i = e; }
    }
    float e2 = expf(b2v - b1v);
    float denom = 1.f + e2;
    float gate1 = 1.f / denom;
    float gate2 = e2 / denom;
#pragma unroll
    for (int e = 0; e < NEXP; e++) g_gates[b * NEXP + e] = 0.f;
    g_gates[b * NEXP + b1i] = gate1;
    g_gates[b * NEXP + b2i] = gate2;
    g_pairE[2 * b] = b1i;     g_pairG[2 * b] = gate1;
    g_pairE[2 * b + 1] = b2i; g_pairG[2 * b + 1] = gate2;
}

// --------------------- expert-sorted pair permutation ----------------------
__global__ void build_perm_kernel()
{
    __shared__ int scnt[NEXP], soff[NEXP], scur[NEXP];
    int t = threadIdx.x;  // 512 threads
    if (t < NEXP) { scnt[t] = 0; scur[t] = 0; }
    __syncthreads();
    atomicAdd(&scnt[g_pairE[t]], 1);
    __syncthreads();
    if (t == 0) {
        int o = 0;
        for (int e = 0; e < NEXP; e++) { soff[e] = o; o += scnt[e]; }
    }
    __syncthreads();
    int e = g_pairE[t];
    int slot = soff[e] + atomicAdd(&scur[e], 1);
    g_perm[slot] = t;
    if (t < NEXP) { g_cnt[t] = scnt[t]; g_off[t] = soff[t]; }
}

// --------------------- grouped expert GEMM (fc1 / fc2) ---------------------
// Per block: 32 rows (pairs of one expert) x 128 cols, K-loop BK=32.
// GATHER: A rows come from feats via perm (token = pair>>1); else direct rows.
template <int KDIM, int NDIM, bool RELU, bool GATHER>
__global__ __launch_bounds__(256) void expert_gemm_kernel(
    const float* __restrict__ Asrc, const float* __restrict__ Wt,
    const float* __restrict__ bias, float* __restrict__ Out)
{
    const int e = blockIdx.y;
    const int cnt = g_cnt[e];
    const int off = g_off[e];
    const int rbase = blockIdx.z * 32;
    if (rbase >= cnt) return;
    const int n0 = blockIdx.x * 128;
    const int t = threadIdx.x;

    __shared__ __align__(16) float As[32][33];
    __shared__ __align__(16) float Bs[32][128];
    __shared__ int srcRow[32];

    if (t < 32) {
        int rr = rbase + t;
        int sr = -1;
        if (rr < cnt) {
            if (GATHER) sr = g_perm[off + rr] >> 1;  // token index
            else        sr = off + rr;               // sorted row index
        }
        srcRow[t] = sr;
    }
    __syncthreads();

    float acc[4][4];
#pragma unroll
    for (int i = 0; i < 4; i++)
#pragma unroll
        for (int j = 0; j < 4; j++) acc[i][j] = 0.f;

    const float* wbase = Wt + (size_t)e * KDIM * NDIM + n0;
    const int rg = t >> 5;   // row group (0..7) -> rows rg*4..+3
    const int cg = t & 31;   // col group (0..31) -> cols cg*4..+3

    for (int kb = 0; kb < KDIM; kb += 32) {
        // A: 32 rows x 32 k
#pragma unroll
        for (int j = 0; j < 4; j++) {
            int eI = j * 256 + t;
            int row = eI >> 5, k = eI & 31;
            int sr = srcRow[row];
            As[k][row] = (sr >= 0) ? Asrc[(size_t)sr * KDIM + kb + k] : 0.f;
        }
        // B: 32 k x 128 n
#pragma unroll
        for (int j = 0; j < 16; j++) {
            int eI = j * 256 + t;
            int k = eI >> 7, n = eI & 127;
            Bs[k][n] = wbase[(size_t)(kb + k) * NDIM + n];
        }
        __syncthreads();
#pragma unroll
        for (int kk = 0; kk < 32; kk++) {
            float bb[4];
            *(float4*)&bb[0] = *(const float4*)&Bs[kk][cg * 4];
            float a0 = As[kk][rg * 4 + 0];
            float a1 = As[kk][rg * 4 + 1];
            float a2 = As[kk][rg * 4 + 2];
            float a3 = As[kk][rg * 4 + 3];
#pragma unroll
            for (int j = 0; j < 4; j++) {
                acc[0][j] += a0 * bb[j];
                acc[1][j] += a1 * bb[j];
                acc[2][j] += a2 * bb[j];
                acc[3][j] += a3 * bb[j];
            }
        }
        __syncthreads();
    }

#pragma unroll
    for (int i = 0; i < 4; i++) {
        int rr = rbase + rg * 4 + i;
        if (rr >= cnt) continue;
        int gr = off + rr;
#pragma unroll
        for (int j = 0; j < 4; j++) {
            int n = n0 + cg * 4 + j;
            float v = acc[i][j] + bias[e * NDIM + n];
            if (RELU) v = v > 0.f ? v : 0.f;
            Out[(size_t)gr * NDIM + n] = v;
        }
    }
}

// -------------------------- zero output buffer -----------------------------
__global__ void zero_kernel(float* __restrict__ p, int n)
{
    int i = blockIdx.x * blockDim.x + threadIdx.x;
    if (i < n) p[i] = 0.f;
}

// ------------------- softmax over experts' logits + combine ----------------
__global__ void softmax_combine_kernel(float* __restrict__ y)
{
    const int gr = blockIdx.x;   // sorted row (0..511)
    const int t = threadIdx.x;   // 256
    const int pair = g_perm[gr];
    const int token = pair >> 1;
    const float gate = g_pairG[pair];
    const float* row = g_o + (size_t)gr * OUTD;

    __shared__ float red[256];
    float m = -INFINITY;
    for (int j = t; j < OUTD; j += 256) m = fmaxf(m, row[j]);
    red[t] = m;
    __syncthreads();
    for (int s = 128; s > 0; s >>= 1) {
        if (t < s) red[t] = fmaxf(red[t], red[t + s]);
        __syncthreads();
    }
    const float M = red[0];
    __syncthreads();

    float s = 0.f;
    for (int j = t; j < OUTD; j += 256) s += expf(row[j] - M);
    red[t] = s;
    __syncthreads();
    for (int st = 128; st > 0; st >>= 1) {
        if (t < st) red[t] += red[t + st];
        __syncthreads();
    }
    const float scale = gate / red[0];

    for (int j = t; j < OUTD; j += 256)
        atomicAdd(&y[(size_t)token * OUTD + j], expf(row[j] - M) * scale);
}

// ------------------------------- aux loss ----------------------------------
__global__ void aux_kernel(float* __restrict__ out, int out_size)
{
    __shared__ float imp[NEXP], loadv[NEXP];
    int t = threadIdx.x;
    if (t < NEXP) {
        float s = 0.f, L = 0.f;
        for (int b = 0; b < BATCH; b++) {
            float gv = g_gates[b * NEXP + t];
            s += gv;
            if (gv > 0.f) L += 1.f;
        }
        imp[t] = s;
        loadv[t] = L;
    }
    __syncthreads();
    if (t == 0 && out_size > BATCH * OUTD) {
        float mi = 0.f, ml = 0.f;
        for (int e = 0; e < NEXP; e++) { mi += imp[e]; ml += loadv[e]; }
        mi /= NEXP; ml /= NEXP;
        float vi = 0.f, vl = 0.f;
        for (int e = 0; e < NEXP; e++) {
            float di = imp[e] - mi, dl = loadv[e] - ml;
            vi += di * di; vl += dl * dl;
        }
        vi /= NEXP; vl /= NEXP;
        float cv_i = vi / (mi * mi + 1e-10f);
        float cv_l = vl / (ml * ml + 1e-10f);
        out[BATCH * OUTD] = 0.01f * (cv_i + cv_l);
    }
}

// ------------------------------- launcher ----------------------------------
extern "C" void kernel_launch(void* const* d_in, const int* in_sizes, int n_in,
                              void* d_out, int out_size)
{
    (void)in_sizes; (void)n_in;
    const float* x   = (const float*)d_in[0];
    const float* cw1 = (const float*)d_in[1];
    const float* cb1 = (const float*)d_in[2];
    const float* cw2 = (const float*)d_in[3];
    const float* cb2 = (const float*)d_in[4];
    const float* cw3 = (const float*)d_in[5];
    const float* cb3 = (const float*)d_in[6];
    const float* cw4 = (const float*)d_in[7];
    const float* cb4 = (const float*)d_in[8];
    const float* cw5 = (const float*)d_in[9];
    const float* cb5 = (const float*)d_in[10];
    const float* w1  = (const float*)d_in[11];
    const float* b1  = (const float*)d_in[12];
    const float* w2  = (const float*)d_in[13];
    const float* b2  = (const float*)d_in[14];
    const float* wg  = (const float*)d_in[15];
    float* y = (float*)d_out;

    float *conv_s, *pool_s, *h_s, *o_s;
    cudaGetSymbolAddress((void**)&conv_s, g_conv);
    cudaGetSymbolAddress((void**)&pool_s, g_pool);
    cudaGetSymbolAddress((void**)&h_s, g_h);
    cudaGetSymbolAddress((void**)&o_s, g_o);

    // ---- conv stack (conv writes g_conv; pool writes g_pool) ----
    // L1: 3 -> 128, 64x64
    conv3x3_relu_kernel<3, 64, 64, 128>
        <<<dim3(256 * 64 * 64 / 128, 128 / 128), 256>>>(x, cw1, cb1, conv_s);
    { int n = 256 * 128 * 32 * 32;
      maxpool2_kernel<<<(n + 255) / 256, 256>>>(conv_s, pool_s, 128, 64, n); }
    // L2: 128 -> 256, 32x32
    conv3x3_relu_kernel<128, 32, 32, 256>
        <<<dim3(256 * 32 * 32 / 128, 2), 256>>>(pool_s, cw2, cb2, conv_s);
    { int n = 256 * 256 * 16 * 16;
      maxpool2_kernel<<<(n + 255) / 256, 256>>>(conv_s, pool_s, 256, 32, n); }
    // L3: 256 -> 256, 16x16
    conv3x3_relu_kernel<256, 16, 16, 256>
        <<<dim3(256 * 16 * 16 / 128, 2), 256>>>(pool_s, cw3, cb3, conv_s);
    { int n = 256 * 256 * 8 * 8;
      maxpool2_kernel<<<(n + 255) / 256, 256>>>(conv_s, pool_s, 256, 16, n); }
    // L4: 256 -> 512, 8x8
    conv3x3_relu_kernel<256, 8, 8, 512>
        <<<dim3(256 * 8 * 8 / 128, 4), 256>>>(pool_s, cw4, cb4, conv_s);
    { int n = 256 * 512 * 4 * 4;
      maxpool2_kernel<<<(n + 255) / 256, 256>>>(conv_s, pool_s, 512, 8, n); }
    // L5: 512 -> 512, 4x4
    conv3x3_relu_kernel<512, 4, 4, 512>
        <<<dim3(256 * 4 * 4 / 128, 4), 256>>>(pool_s, cw5, cb5, conv_s);
    { int n = 256 * 512 * 2 * 2;
      maxpool2_kernel<<<(n + 255) / 256, 256>>>(conv_s, pool_s, 512, 4, n); }
    // feats = g_pool, [256, 2048]

    // ---- gating ----
    gate_logits_kernel<<<NEXP, 256>>>(pool_s, wg);
    topk_kernel<<<1, 256>>>();
    build_perm_kernel<<<1, 512>>>();

    // ---- sparse expert MLPs (512 active pairs) ----
    expert_gemm_kernel<DFEAT, HID, true, true>
        <<<dim3(HID / 128, NEXP, 8), 256>>>(pool_s, w1, b1, h_s);
    expert_gemm_kernel<HID, OUTD, false, false>
        <<<dim3(OUTD / 128, NEXP, 8), 256>>>(h_s, w2, b2, o_s);

    // ---- combine + aux ----
    zero_kernel<<<(out_size + 255) / 256, 256>>>(y, out_size);
    softmax_combine_kernel<<<NPAIR, 256>>>(y);
    aux_kernel<<<1, 256>>>(y, out_size);
}

// round 3
// speedup vs baseline: 2.3913x; 2.3913x over previous
#include <cuda_runtime.h>
#include <cuda_bf16.h>
#include <math.h>
#include <stdint.h>

// ---------------------------------------------------------------------------
// ToyMoE: conv stack (5x conv3x3+relu+maxpool2) -> top-2 gating (eval)
//         -> sparse top-2 expert MLPs -> softmax -> gated combine + aux loss
// B=256, D=2048, HID=4096, O=1024, E=16
// conv2-5: bf16 mma.sync (3-term split => fp32-class accuracy), conv1 fp32.
// NOTE: harness PTX target is sm_103 (no 'a') -> tcgen05 unavailable; use
// mma.sync/ldmatrix/cp.async (sm_80+ features, legal on sm_103).
// ---------------------------------------------------------------------------

#define BATCH 256
#define DFEAT 2048
#define HID 4096
#define OUTD 1024
#define NEXP 16
#define NPAIR (BATCH * 2)

// ------------------------- scratch (device globals) ------------------------
__device__ float    g_conv[(size_t)256 * 128 * 64 * 64];   // 512 MB conv outputs (NCHW)
__device__ unsigned g_packed[(size_t)256 * 32 * 32 * 128]; // 134 MB NHWC packed bf16 hi|lo
__device__ unsigned g_wpack1[(size_t)512 * 512 * 9];       // 9.4 MB (hi,hi) pairs
__device__ unsigned g_wpack2[(size_t)512 * 512 * 9];       // 9.4 MB (lo, 0) pairs
__device__ float    g_pool[BATCH * DFEAT];                 // feats
__device__ float    g_logits[BATCH * NEXP];
__device__ float    g_gates[BATCH * NEXP];
__device__ int      g_pairE[NPAIR];
__device__ float    g_pairG[NPAIR];
__device__ int      g_perm[NPAIR];
__device__ int      g_cnt[NEXP];
__device__ int      g_off[NEXP];
__device__ float    g_h[(size_t)NPAIR * HID];
__device__ float    g_o[(size_t)NPAIR * OUTD];

// ------------------------------ PTX helpers --------------------------------
__device__ __forceinline__ uint32_t smem_u32(const void* p) {
    uint32_t a;
    asm("{ .reg .u64 t; cvta.to.shared.u64 t, %1; cvt.u32.u64 %0, t; }"
        : "=r"(a) : "l"(p));
    return a;
}

#define SWZ(x) ((x) ^ (((x) >> 3) & 0x70))

__device__ __forceinline__ void cp16(uint32_t dst, const void* src, int sz) {
    asm volatile("cp.async.cg.shared.global [%0], [%1], 16, %2;"
                 :: "r"(dst), "l"(src), "r"(sz) : "memory");
}
#define CP_COMMIT() asm volatile("cp.async.commit_group;" ::: "memory")
#define CP_WAIT1()  asm volatile("cp.async.wait_group 1;" ::: "memory")

__device__ __forceinline__ void ldsm4(uint32_t& r0, uint32_t& r1,
                                      uint32_t& r2, uint32_t& r3, uint32_t a) {
    asm volatile("ldmatrix.sync.aligned.m8n8.x4.shared.b16 {%0,%1,%2,%3}, [%4];"
                 : "=r"(r0), "=r"(r1), "=r"(r2), "=r"(r3) : "r"(a));
}
__device__ __forceinline__ void mma16816(float* d, const uint32_t* a,
                                         const uint32_t* b) {
    asm volatile(
        "mma.sync.aligned.m16n8k16.row.col.f32.bf16.bf16.f32 "
        "{%0,%1,%2,%3}, {%4,%5,%6,%7}, {%8,%9}, {%0,%1,%2,%3};"
        : "+f"(d[0]), "+f"(d[1]), "+f"(d[2]), "+f"(d[3])
        : "r"(a[0]), "r"(a[1]), "r"(a[2]), "r"(a[3]), "r"(b[0]), "r"(b[1]));
}

// --------------------- bf16 mma.sync conv3x3 (SAME, relu) ------------------
// Implicit GEMM: M = B*H*W, N = CO, virtual K' = 2*9*CI (even=hi, odd=lo).
// A = packed NHWC u32 (raw cp.async copy). W1=(hi,hi), W2=(lo,0) pairs:
//   A'.W1 = hi*hi + lo*hi ; A'.W2 = hi*lo  => full 3-term split.
// CTA 128x128, chunk = 64 bf16 k' (= 32 channels of one tap), 2-stage pipe.
#define CONV_DSM (2 * 49152 + 1024)

template <int CI, int H, int W, int CO>
__global__ __launch_bounds__(256, 1) void conv_mma_kernel(
    const unsigned* __restrict__ inpk, const unsigned* __restrict__ w1pk,
    const unsigned* __restrict__ w2pk, const float* __restrict__ bias,
    float* __restrict__ out)
{
    constexpr int HW = H * W;
    constexpr int CPT = CI / 32;      // chunks per tap
    constexpr int NCH = 9 * CPT;
    constexpr int WROW = 9 * CI;      // u32 per weight row

    extern __shared__ char dsm[];
    const uint32_t sb = (smem_u32(dsm) + 1023u) & ~1023u;
    const int t = threadIdx.x;
    const int lane = t & 31;
    const int wid = t >> 5;
    const int wm = wid & 1, wn = wid >> 1;       // 2 x 4 warp grid
    const int m0 = blockIdx.x * 128, n0 = blockIdx.y * 128;
    const int seg = t & 7;                       // 16B segment in 128B row
    const int rsub = t >> 3;                     // 0..31

    // producer row metadata (4 rows per thread)
    int bb[4], yy[4], xx[4];
    size_t wrow[4];
    uint32_t dsw[4];
#pragma unroll
    for (int i = 0; i < 4; i++) {
        const int m = m0 + i * 32 + rsub;
        bb[i] = m / HW;
        const int pos = m % HW;
        yy[i] = pos / W;
        xx[i] = pos % W;
        wrow[i] = (size_t)(n0 + i * 32 + rsub) * WROW + seg * 4;
        dsw[i] = SWZ((uint32_t)((i * 32 + rsub) * 128 + seg * 16));
    }

    auto fill = [&](int s, int c) {
        const uint32_t stg = sb + s * 49152;
        const int tap = c / CPT;
        const int cib = (c % CPT) * 32;
        const int dy = tap / 3 - 1, dx = tap % 3 - 1;
#pragma unroll
        for (int i = 0; i < 4; i++) {
            const int iy = yy[i] + dy, ix = xx[i] + dx;
            const bool ok = (iy >= 0 && iy < H && ix >= 0 && ix < W);
            const unsigned* src = inpk +
                (((size_t)bb[i] * H + (ok ? iy : 0)) * W + (ok ? ix : 0)) * CI +
                cib + seg * 4;
            cp16(stg + dsw[i], src, ok ? 16 : 0);
        }
        const size_t co32 = (size_t)c * 32;
#pragma unroll
        for (int i = 0; i < 4; i++) {
            cp16(stg + 16384 + dsw[i], w1pk + wrow[i] + co32, 16);
            cp16(stg + 32768 + dsw[i], w2pk + wrow[i] + co32, 16);
        }
    };

    float acc[4][4][4];
#pragma unroll
    for (int a = 0; a < 4; a++)
#pragma unroll
        for (int b = 0; b < 4; b++)
#pragma unroll
            for (int cj = 0; cj < 4; cj++) acc[a][b][cj] = 0.f;

    fill(0, 0);
    CP_COMMIT();

    for (int c = 0; c < NCH; c++) {
        const int s = c & 1;
        if (c + 1 < NCH) fill(s ^ 1, c + 1);
        CP_COMMIT();
        CP_WAIT1();
        __syncthreads();

        const uint32_t bA = sb + s * 49152;
        const uint32_t bB1 = bA + 16384;
        const uint32_t bB2 = bA + 32768;
#pragma unroll
        for (int ks = 0; ks < 4; ks++) {
            const int c0 = ks * 32;  // byte col of k0
            uint32_t a[4][4];
#pragma unroll
            for (int mt = 0; mt < 4; mt++) {
                const int row = wm * 64 + mt * 16 + (lane & 15);
                const uint32_t ad =
                    bA + SWZ((uint32_t)(row * 128 + c0 + (lane >> 4) * 16));
                ldsm4(a[mt][0], a[mt][1], a[mt][2], a[mt][3], ad);
            }
            uint32_t b1[8], b2[8];
#pragma unroll
            for (int p = 0; p < 2; p++) {
                const int row =
                    wn * 32 + p * 16 + (lane & 7) + (lane >> 4) * 8;
                const uint32_t off =
                    SWZ((uint32_t)(row * 128 + c0 + ((lane >> 3) & 1) * 16));
                ldsm4(b1[p * 4], b1[p * 4 + 1], b1[p * 4 + 2], b1[p * 4 + 3],
                      bB1 + off);
                ldsm4(b2[p * 4], b2[p * 4 + 1], b2[p * 4 + 2], b2[p * 4 + 3],
                      bB2 + off);
            }
#pragma unroll
            for (int mt = 0; mt < 4; mt++)
#pragma unroll
                for (int nt = 0; nt < 4; nt++) {
                    mma16816(acc[mt][nt], a[mt], &b1[nt * 2]);
                    mma16816(acc[mt][nt], a[mt], &b2[nt * 2]);
                }
        }
        __syncthreads();
    }

    // epilogue: bias + relu -> NCHW
    const int mrow = lane >> 2;
    const int ncol = (lane & 3) * 2;
#pragma unroll
    for (int mt = 0; mt < 4; mt++) {
#pragma unroll
        for (int half = 0; half < 2; half++) {
            const int m = m0 + wm * 64 + mt * 16 + mrow + half * 8;
            const int bimg = m / HW;
            const int pos = m % HW;
            float* ob = out + (size_t)bimg * CO * HW + pos;
#pragma unroll
            for (int nt = 0; nt < 4; nt++) {
#pragma unroll
                for (int j = 0; j < 2; j++) {
                    const int n = n0 + wn * 32 + nt * 8 + ncol + j;
                    float v = acc[mt][nt][half * 2 + j] + bias[n];
                    ob[(size_t)n * HW] = v > 0.f ? v : 0.f;
                }
            }
        }
    }
}

// --------------- pool(2x2) + bf16-split pack + NCHW->NHWC ------------------
__global__ void pool_pack_kernel(const float* __restrict__ in,
                                 unsigned* __restrict__ out,
                                 int C, int Hin, int PosOut)
{
    __shared__ unsigned sm[32][33];
    const int b = blockIdx.z;
    const int Wo = Hin >> 1;
    const int c = blockIdx.y * 32 + threadIdx.y;
    const int po = blockIdx.x * 32 + threadIdx.x;
    unsigned pk = 0;
    if (po < PosOut) {
        const int yo = po / Wo, xo = po % Wo;
        const float* p = in + (((size_t)b * C + c) * Hin + 2 * yo) * Hin + 2 * xo;
        float v = fmaxf(fmaxf(p[0], p[1]), fmaxf(p[Hin], p[Hin + 1]));
        __nv_bfloat16 h = __float2bfloat16_rn(v);
        __nv_bfloat16 l = __float2bfloat16_rn(v - __bfloat162float(h));
        pk = (unsigned)__bfloat16_as_ushort(h) |
             ((unsigned)__bfloat16_as_ushort(l) << 16);
    }
    sm[threadIdx.y][threadIdx.x] = pk;
    __syncthreads();
    const int po2 = blockIdx.x * 32 + threadIdx.y;
    const int c2 = blockIdx.y * 32 + threadIdx.x;
    if (po2 < PosOut)
        out[((size_t)b * PosOut + po2) * C + c2] = sm[threadIdx.x][threadIdx.y];
}

// -------- weight pack: OIHW -> [co][tap*CI+ci] pairs, W1=(hi,hi) W2=(lo,0) --
__global__ void wpack2_kernel(const float* __restrict__ w,
                              unsigned* __restrict__ o1,
                              unsigned* __restrict__ o2, int CO, int CI)
{
    const int i = blockIdx.x * 256 + threadIdx.x;
    if (i >= CO * CI * 9) return;
    const int tap = i % 9;
    const int ci = (i / 9) % CI;
    const int co = i / (9 * CI);
    const float v = w[i];
    const __nv_bfloat16 h = __float2bfloat16_rn(v);
    const __nv_bfloat16 l = __float2bfloat16_rn(v - __bfloat162float(h));
    const unsigned hu = (unsigned)__bfloat16_as_ushort(h);
    const unsigned lu = (unsigned)__bfloat16_as_ushort(l);
    const size_t o = (size_t)co * CI * 9 + (size_t)tap * CI + ci;
    o1[o] = hu | (hu << 16);
    o2[o] = lu;  // high half = +0.0 bf16
}

// ------------------- conv3x3 fp32 SIMT (layer 1 only) ----------------------
template <int CI, int H, int W, int CO>
__global__ __launch_bounds__(256) void conv3x3_relu_kernel(
    const float* __restrict__ in, const float* __restrict__ wt,
    const float* __restrict__ bias, float* __restrict__ out)
{
    constexpr int BM = 128, BN = 128, CIB = 4, BK = CIB * 9;
    constexpr int HW = H * W;

    __shared__ __align__(16) float As[BK][BM + 4];
    __shared__ __align__(16) float Bs[BK][BN + 4];

    const int t = threadIdx.x;
    const int m0 = blockIdx.x * BM;
    const int n0 = blockIdx.y * BN;
    const int tx = t & 15;
    const int ty = t >> 4;

    float acc[8][8];
#pragma unroll
    for (int i = 0; i < 8; i++)
#pragma unroll
        for (int j = 0; j < 8; j++) acc[i][j] = 0.f;

    for (int cb = 0; cb < CI; cb += CIB) {
#pragma unroll
        for (int j = 0; j < 18; j++) {
            int e = j * 256 + t;
            int k = e >> 7;
            int p = e & 127;
            int ci = cb + k / 9;
            int rc = k % 9;
            int s = m0 + p;
            int b = s / HW;
            int rr = s % HW;
            int y = rr / W, x = rr % W;
            int iy = y + rc / 3 - 1;
            int ix = x + rc % 3 - 1;
            float v = 0.f;
            if (ci < CI && iy >= 0 && iy < H && ix >= 0 && ix < W)
                v = in[((size_t)(b * CI + ci) * H + iy) * W + ix];
            As[k][p] = v;
        }
        {
            int n = t >> 1;
            int kbase = (t & 1) * 18;
            int co = n0 + n;
            const float* wp = wt + ((size_t)co * CI + cb) * 9;
#pragma unroll
            for (int j = 0; j < 18; j++) {
                int k = kbase + j;
                int ci = cb + k / 9;
                Bs[k][n] = (ci < CI) ? wp[k] : 0.f;
            }
        }
        __syncthreads();
#pragma unroll 4
        for (int kk = 0; kk < BK; kk++) {
            float a[8], bbv[8];
            *(float4*)&a[0] = *(const float4*)&As[kk][tx * 8];
            *(float4*)&a[4] = *(const float4*)&As[kk][tx * 8 + 4];
            *(float4*)&bbv[0] = *(const float4*)&Bs[kk][ty * 8];
            *(float4*)&bbv[4] = *(const float4*)&Bs[kk][ty * 8 + 4];
#pragma unroll
            for (int i = 0; i < 8; i++)
#pragma unroll
                for (int j = 0; j < 8; j++) acc[i][j] += a[i] * bbv[j];
        }
        __syncthreads();
    }
#pragma unroll
    for (int i = 0; i < 8; i++) {
        int m = m0 + tx * 8 + i;
        int b = m / HW;
        int rr = m % HW;
        int y = rr / W, x = rr % W;
        size_t obase = (size_t)b * CO * HW + (size_t)y * W + x;
#pragma unroll
        for (int j = 0; j < 8; j++) {
            int co = n0 + ty * 8 + j;
            float v = acc[i][j] + bias[co];
            out[obase + (size_t)co * HW] = v > 0.f ? v : 0.f;
        }
    }
}

// ------------------------------ maxpool 2x2 --------------------------------
__global__ void maxpool2_kernel(const float* __restrict__ in,
                                float* __restrict__ out, int C, int H, int n)
{
    int Ho = H / 2;
    for (int i = blockIdx.x * blockDim.x + threadIdx.x; i < n;
         i += gridDim.x * blockDim.x) {
        int x = i % Ho;
        int y = (i / Ho) % Ho;
        int c = (i / (Ho * Ho)) % C;
        int b = i / (Ho * Ho * C);
        const float* p = in + ((size_t)(b * C + c) * H + 2 * y) * H + 2 * x;
        out[i] = fmaxf(fmaxf(p[0], p[1]), fmaxf(p[H], p[H + 1]));
    }
}

// ----------------------------- gate logits ---------------------------------
__global__ void gate_logits_kernel(const float* __restrict__ feats,
                                   const float* __restrict__ wg)
{
    int t = blockIdx.x * blockDim.x + threadIdx.x;
    if (t >= BATCH * NEXP) return;
    int b = t >> 4, e = t & 15;
    const float* f = feats + (size_t)b * DFEAT;
    float s = 0.f;
    for (int d = 0; d < DFEAT; d++) s += f[d] * wg[d * NEXP + e];
    g_logits[t] = s;
}

// --------------------------- top-2 + gate softmax --------------------------
__global__ void topk_kernel()
{
    int b = threadIdx.x;
    if (b >= BATCH) return;
    float l[NEXP];
#pragma unroll
    for (int e = 0; e < NEXP; e++) l[e] = g_logits[b * NEXP + e];
    float b1v = -INFINITY, b2v = -INFINITY;
    int b1i = 0, b2i = 0;
#pragma unroll
    for (int e = 0; e < NEXP; e++) {
        float v = l[e];
        if (v > b1v) { b2v = b1v; b2i = b1i; b1v = v; b1i = e; }
        else if (v > b2v) { b2v = v; b2i = e; }
    }
    float e2 = expf(b2v - b1v);
    float denom = 1.f + e2;
    float gate1 = 1.f / denom;
    float gate2 = e2 / denom;
#pragma unroll
    for (int e = 0; e < NEXP; e++) g_gates[b * NEXP + e] = 0.f;
    g_gates[b * NEXP + b1i] = gate1;
    g_gates[b * NEXP + b2i] = gate2;
    g_pairE[2 * b] = b1i;     g_pairG[2 * b] = gate1;
    g_pairE[2 * b + 1] = b2i; g_pairG[2 * b + 1] = gate2;
}

// --------------------- expert-sorted pair permutation ----------------------
__global__ void build_perm_kernel()
{
    __shared__ int scnt[NEXP], soff[NEXP], scur[NEXP];
    int t = threadIdx.x;
    if (t < NEXP) { scnt[t] = 0; scur[t] = 0; }
    __syncthreads();
    atomicAdd(&scnt[g_pairE[t]], 1);
    __syncthreads();
    if (t == 0) {
        int o = 0;
        for (int e = 0; e < NEXP; e++) { soff[e] = o; o += scnt[e]; }
    }
    __syncthreads();
    int e = g_pairE[t];
    int slot = soff[e] + atomicAdd(&scur[e], 1);
    g_perm[slot] = t;
    if (t < NEXP) { g_cnt[t] = scnt[t]; g_off[t] = soff[t]; }
}

// --------------------- grouped expert GEMM (fc1 / fc2) ---------------------
template <int KDIM, int NDIM, bool RELU, bool GATHER>
__global__ __launch_bounds__(256) void expert_gemm_kernel(
    const float* __restrict__ Asrc, const float* __restrict__ Wt,
    const float* __restrict__ bias, float* __restrict__ Out)
{
    const int e = blockIdx.y;
    const int cnt = g_cnt[e];
    const int off = g_off[e];
    const int rbase = blockIdx.z * 32;
    if (rbase >= cnt) return;
    const int n0 = blockIdx.x * 128;
    const int t = threadIdx.x;

    __shared__ __align__(16) float As[32][33];
    __shared__ __align__(16) float Bs[32][128];
    __shared__ int srcRow[32];

    if (t < 32) {
        int rr = rbase + t;
        int sr = -1;
        if (rr < cnt) {
            if (GATHER) sr = g_perm[off + rr] >> 1;
            else        sr = off + rr;
        }
        srcRow[t] = sr;
    }
    __syncthreads();

    float acc[4][4];
#pragma unroll
    for (int i = 0; i < 4; i++)
#pragma unroll
        for (int j = 0; j < 4; j++) acc[i][j] = 0.f;

    const float* wbase = Wt + (size_t)e * KDIM * NDIM + n0;
    const int rg = t >> 5;
    const int cg = t & 31;

    for (int kb = 0; kb < KDIM; kb += 32) {
#pragma unroll
        for (int j = 0; j < 4; j++) {
            int eI = j * 256 + t;
            int row = eI >> 5, k = eI & 31;
            int sr = srcRow[row];
            As[k][row] = (sr >= 0) ? Asrc[(size_t)sr * KDIM + kb + k] : 0.f;
        }
#pragma unroll
        for (int j = 0; j < 16; j++) {
            int eI = j * 256 + t;
            int k = eI >> 7, n = eI & 127;
            Bs[k][n] = wbase[(size_t)(kb + k) * NDIM + n];
        }
        __syncthreads();
#pragma unroll
        for (int kk = 0; kk < 32; kk++) {
            float bbv[4];
            *(float4*)&bbv[0] = *(const float4*)&Bs[kk][cg * 4];
            float a0 = As[kk][rg * 4 + 0];
            float a1 = As[kk][rg * 4 + 1];
            float a2 = As[kk][rg * 4 + 2];
            float a3 = As[kk][rg * 4 + 3];
#pragma unroll
            for (int j = 0; j < 4; j++) {
                acc[0][j] += a0 * bbv[j];
                acc[1][j] += a1 * bbv[j];
                acc[2][j] += a2 * bbv[j];
                acc[3][j] += a3 * bbv[j];
            }
        }
        __syncthreads();
    }
#pragma unroll
    for (int i = 0; i < 4; i++) {
        int rr = rbase + rg * 4 + i;
        if (rr >= cnt) continue;
        int gr = off + rr;
#pragma unroll
        for (int j = 0; j < 4; j++) {
            int n = n0 + cg * 4 + j;
            float v = acc[i][j] + bias[e * NDIM + n];
            if (RELU) v = v > 0.f ? v : 0.f;
            Out[(size_t)gr * NDIM + n] = v;
        }
    }
}

// -------------------------- zero output buffer -----------------------------
__global__ void zero_kernel(float* __restrict__ p, int n)
{
    int i = blockIdx.x * blockDim.x + threadIdx.x;
    if (i < n) p[i] = 0.f;
}

// ------------------- softmax over experts' logits + combine ----------------
__global__ void softmax_combine_kernel(float* __restrict__ y)
{
    const int gr = blockIdx.x;
    const int t = threadIdx.x;
    const int pair = g_perm[gr];
    const int token = pair >> 1;
    const float gate = g_pairG[pair];
    const float* row = g_o + (size_t)gr * OUTD;

    __shared__ float red[256];
    float m = -INFINITY;
    for (int j = t; j < OUTD; j += 256) m = fmaxf(m, row[j]);
    red[t] = m;
    __syncthreads();
    for (int s = 128; s > 0; s >>= 1) {
        if (t < s) red[t] = fmaxf(red[t], red[t + s]);
        __syncthreads();
    }
    const float M = red[0];
    __syncthreads();

    float s = 0.f;
    for (int j = t; j < OUTD; j += 256) s += expf(row[j] - M);
    red[t] = s;
    __syncthreads();
    for (int st = 128; st > 0; st >>= 1) {
        if (t < st) red[t] += red[t + st];
        __syncthreads();
    }
    const float scale = gate / red[0];

    for (int j = t; j < OUTD; j += 256)
        atomicAdd(&y[(size_t)token * OUTD + j], expf(row[j] - M) * scale);
}

// ------------------------------- aux loss ----------------------------------
__global__ void aux_kernel(float* __restrict__ out, int out_size)
{
    __shared__ float imp[NEXP], loadv[NEXP];
    int t = threadIdx.x;
    if (t < NEXP) {
        float s = 0.f, L = 0.f;
        for (int b = 0; b < BATCH; b++) {
            float gv = g_gates[b * NEXP + t];
            s += gv;
            if (gv > 0.f) L += 1.f;
        }
        imp[t] = s;
        loadv[t] = L;
    }
    __syncthreads();
    if (t == 0 && out_size > BATCH * OUTD) {
        float mi = 0.f, ml = 0.f;
        for (int e = 0; e < NEXP; e++) { mi += imp[e]; ml += loadv[e]; }
        mi /= NEXP; ml /= NEXP;
        float vi = 0.f, vl = 0.f;
        for (int e = 0; e < NEXP; e++) {
            float di = imp[e] - mi, dl = loadv[e] - ml;
            vi += di * di; vl += dl * dl;
        }
        vi /= NEXP; vl /= NEXP;
        out[BATCH * OUTD] =
            0.01f * (vi / (mi * mi + 1e-10f) + vl / (ml * ml + 1e-10f));
    }
}

// ------------------------------- launcher ----------------------------------
extern "C" void kernel_launch(void* const* d_in, const int* in_sizes, int n_in,
                              void* d_out, int out_size)
{
    (void)in_sizes; (void)n_in;
    const float* x   = (const float*)d_in[0];
    const float* cw1 = (const float*)d_in[1];
    const float* cb1 = (const float*)d_in[2];
    const float* cw2 = (const float*)d_in[3];
    const float* cb2 = (const float*)d_in[4];
    const float* cw3 = (const float*)d_in[5];
    const float* cb3 = (const float*)d_in[6];
    const float* cw4 = (const float*)d_in[7];
    const float* cb4 = (const float*)d_in[8];
    const float* cw5 = (const float*)d_in[9];
    const float* cb5 = (const float*)d_in[10];
    const float* w1  = (const float*)d_in[11];
    const float* b1  = (const float*)d_in[12];
    const float* w2  = (const float*)d_in[13];
    const float* b2  = (const float*)d_in[14];
    const float* wg  = (const float*)d_in[15];
    float* y = (float*)d_out;

    float *conv_s, *pool_s, *h_s, *o_s;
    unsigned *pk_s, *wp1_s, *wp2_s;
    cudaGetSymbolAddress((void**)&conv_s, g_conv);
    cudaGetSymbolAddress((void**)&pool_s, g_pool);
    cudaGetSymbolAddress((void**)&h_s, g_h);
    cudaGetSymbolAddress((void**)&o_s, g_o);
    cudaGetSymbolAddress((void**)&pk_s, g_packed);
    cudaGetSymbolAddress((void**)&wp1_s, g_wpack1);
    cudaGetSymbolAddress((void**)&wp2_s, g_wpack2);

    cudaFuncSetAttribute(conv_mma_kernel<128, 32, 32, 256>,
                         cudaFuncAttributeMaxDynamicSharedMemorySize, CONV_DSM);
    cudaFuncSetAttribute(conv_mma_kernel<256, 16, 16, 256>,
                         cudaFuncAttributeMaxDynamicSharedMemorySize, CONV_DSM);
    cudaFuncSetAttribute(conv_mma_kernel<256, 8, 8, 512>,
                         cudaFuncAttributeMaxDynamicSharedMemorySize, CONV_DSM);
    cudaFuncSetAttribute(conv_mma_kernel<512, 4, 4, 512>,
                         cudaFuncAttributeMaxDynamicSharedMemorySize, CONV_DSM);

    // ---- L1: fp32 SIMT conv (CI=3), then pool+pack ----
    conv3x3_relu_kernel<3, 64, 64, 128>
        <<<dim3(256 * 64 * 64 / 128, 1), 256>>>(x, cw1, cb1, conv_s);
    pool_pack_kernel<<<dim3(32, 4, 256), dim3(32, 32)>>>(conv_s, pk_s, 128, 64, 1024);

    // ---- L2: 128 -> 256 @32x32 ----
    wpack2_kernel<<<(256 * 128 * 9 + 255) / 256, 256>>>(cw2, wp1_s, wp2_s, 256, 128);
    conv_mma_kernel<128, 32, 32, 256>
        <<<dim3(2048, 2), 256, CONV_DSM>>>(pk_s, wp1_s, wp2_s, cb2, conv_s);
    pool_pack_kernel<<<dim3(8, 8, 256), dim3(32, 32)>>>(conv_s, pk_s, 256, 32, 256);

    // ---- L3: 256 -> 256 @16x16 ----
    wpack2_kernel<<<(256 * 256 * 9 + 255) / 256, 256>>>(cw3, wp1_s, wp2_s, 256, 256);
    conv_mma_kernel<256, 16, 16, 256>
        <<<dim3(512, 2), 256, CONV_DSM>>>(pk_s, wp1_s, wp2_s, cb3, conv_s);
    pool_pack_kernel<<<dim3(2, 8, 256), dim3(32, 32)>>>(conv_s, pk_s, 256, 16, 64);

    // ---- L4: 256 -> 512 @8x8 ----
    wpack2_kernel<<<(512 * 256 * 9 + 255) / 256, 256>>>(cw4, wp1_s, wp2_s, 512, 256);
    conv_mma_kernel<256, 8, 8, 512>
        <<<dim3(128, 4), 256, CONV_DSM>>>(pk_s, wp1_s, wp2_s, cb4, conv_s);
    pool_pack_kernel<<<dim3(1, 16, 256), dim3(32, 32)>>>(conv_s, pk_s, 512, 8, 16);

    // ---- L5: 512 -> 512 @4x4 ----
    wpack2_kernel<<<(512 * 512 * 9 + 255) / 256, 256>>>(cw5, wp1_s, wp2_s, 512, 512);
    conv_mma_kernel<512, 4, 4, 512>
        <<<dim3(32, 4), 256, CONV_DSM>>>(pk_s, wp1_s, wp2_s, cb5, conv_s);
    { int n = 256 * 512 * 2 * 2;
      maxpool2_kernel<<<(n + 255) / 256, 256>>>(conv_s, pool_s, 512, 4, n); }

    // ---- gating ----
    gate_logits_kernel<<<NEXP, 256>>>(pool_s, wg);
    topk_kernel<<<1, 256>>>();
    build_perm_kernel<<<1, 512>>>();

    // ---- sparse expert MLPs (512 active pairs) ----
    expert_gemm_kernel<DFEAT, HID, true, true>
        <<<dim3(HID / 128, NEXP, 8), 256>>>(pool_s, w1, b1, h_s);
    expert_gemm_kernel<HID, OUTD, false, false>
        <<<dim3(OUTD / 128, NEXP, 8), 256>>>(h_s, w2, b2, o_s);

    // ---- combine + aux ----
    zero_kernel<<<(out_size + 255) / 256, 256>>>(y, out_size);
    softmax_combine_kernel<<<NPAIR, 256>>>(y);
    aux_kernel<<<1, 256>>>(y, out_size);
}

// round 4
// speedup vs baseline: 2.9413x; 1.2300x over previous
#include <cuda_runtime.h>
#include <cuda_bf16.h>
#include <math.h>
#include <stdint.h>

// ---------------------------------------------------------------------------
// ToyMoE: conv stack (5x conv3x3+relu+maxpool2) -> top-2 gating (eval)
//         -> sparse top-2 expert MLPs -> softmax -> gated combine + aux loss
// conv2-5: bf16 mma.sync, 3-term split (hi*hi + hi*lo + lo*hi), fused
// pool+pack epilogue. conv1: fp32 SIMT with fused pool+pack epilogue.
// ---------------------------------------------------------------------------

#define BATCH 256
#define DFEAT 2048
#define HID 4096
#define OUTD 1024
#define NEXP 16
#define NPAIR (BATCH * 2)

// ------------------------- scratch (device globals) ------------------------
__device__ unsigned       g_pkA[(size_t)256 * 1024 * 128]; // 134 MB NHWC packed (L1/L3 out)
__device__ unsigned       g_pkB[(size_t)256 * 256 * 256];  // 67 MB  NHWC packed (L2/L4 out)
__device__ unsigned       g_whh[(size_t)512 * 512 * 9];    // 9.4 MB (hi,hi) weight pairs
__device__ unsigned short g_wlo[(size_t)512 * 512 * 9];    // 4.7 MB lo weights
__device__ float          g_pool[BATCH * DFEAT];           // feats
__device__ float          g_logits[BATCH * NEXP];
__device__ float          g_gates[BATCH * NEXP];
__device__ int            g_pairE[NPAIR];
__device__ float          g_pairG[NPAIR];
__device__ int            g_perm[NPAIR];
__device__ int            g_cnt[NEXP];
__device__ int            g_off[NEXP];
__device__ float          g_h[(size_t)NPAIR * HID];
__device__ float          g_o[(size_t)NPAIR * OUTD];

// ------------------------------ PTX helpers --------------------------------
__device__ __forceinline__ uint32_t smem_u32(const void* p) {
    uint32_t a;
    asm("{ .reg .u64 t; cvta.to.shared.u64 t, %1; cvt.u32.u64 %0, t; }"
        : "=r"(a) : "l"(p));
    return a;
}

#define SWZ128(x) ((x) ^ (((x) >> 3) & 0x70))
#define SWZ64(x)  ((x) ^ (((x) >> 3) & 0x30))

__device__ __forceinline__ void cp16(uint32_t dst, const void* src, int sz) {
    asm volatile("cp.async.cg.shared.global [%0], [%1], 16, %2;"
                 :: "r"(dst), "l"(src), "r"(sz) : "memory");
}
#define CP_COMMIT() asm volatile("cp.async.commit_group;" ::: "memory")
#define CP_WAIT(n)  asm volatile("cp.async.wait_group %0;" :: "n"(n) : "memory")

__device__ __forceinline__ uint4 lds128(uint32_t a) {
    uint4 r;
    asm volatile("ld.shared.v4.b32 {%0,%1,%2,%3}, [%4];"
                 : "=r"(r.x), "=r"(r.y), "=r"(r.z), "=r"(r.w) : "r"(a));
    return r;
}
__device__ __forceinline__ void sts128(uint32_t a, uint4 v) {
    asm volatile("st.shared.v4.b32 [%0], {%1,%2,%3,%4};"
                 :: "r"(a), "r"(v.x), "r"(v.y), "r"(v.z), "r"(v.w) : "memory");
}
__device__ __forceinline__ void ldsm4(uint32_t& r0, uint32_t& r1,
                                      uint32_t& r2, uint32_t& r3, uint32_t a) {
    asm volatile("ldmatrix.sync.aligned.m8n8.x4.shared.b16 {%0,%1,%2,%3}, [%4];"
                 : "=r"(r0), "=r"(r1), "=r"(r2), "=r"(r3) : "r"(a));
}
__device__ __forceinline__ void mma16816(float* d, const uint32_t* a,
                                         const uint32_t* b) {
    asm volatile(
        "mma.sync.aligned.m16n8k16.row.col.f32.bf16.bf16.f32 "
        "{%0,%1,%2,%3}, {%4,%5,%6,%7}, {%8,%9}, {%0,%1,%2,%3};"
        : "+f"(d[0]), "+f"(d[1]), "+f"(d[2]), "+f"(d[3])
        : "r"(a[0]), "r"(a[1]), "r"(a[2]), "r"(a[3]), "r"(b[0]), "r"(b[1]));
}

// --------------------- bf16 mma.sync conv3x3 (SAME, relu, fused pool) ------
// Implicit GEMM M=B*H*W, N=CO, chunk = 32 real k (one tap, 32 channels).
// Pass1 (virtual K'=64): A_pk (raw packed hi|lo) x B1=(hi,hi) => hi*hi+lo*hi
// Pass2 (real K=32):     A_hi (unpacked in SMEM)  x W_lo      => hi*lo
// 3-stage cp.async pipeline. Epilogue: bias+relu -> SMEM -> 2x2 pool ->
// packed NHWC u32 out (or fp32 feats for the last layer).
#define STG_SZ 49152
#define CONV_DSM (3 * STG_SZ + 1024)

template <int CI, int H, int W, int CO, bool FEATS>
__global__ __launch_bounds__(256, 1) void conv_mma_kernel(
    const unsigned* __restrict__ inpk, const unsigned* __restrict__ whh,
    const unsigned short* __restrict__ wlo, const float* __restrict__ bias,
    unsigned* __restrict__ outpk, float* __restrict__ outf)
{
    constexpr int HW = H * W;
    constexpr int CPT = CI / 32;
    constexpr int NCH = 9 * CPT;
    constexpr int WROW = 9 * CI;

    extern __shared__ __align__(1024) char dsm[];
    const uint32_t sb = smem_u32(dsm);
    const int t = threadIdx.x;
    const int lane = t & 31;
    const int wid = t >> 5;
    const int wm = wid & 1, wn = wid >> 1;  // 2 x 4 warp grid
    const int m0 = blockIdx.x * 128, n0 = blockIdx.y * 128;
    const int seg = t & 7;
    const int rsub = t >> 3;

    int bb[4], yy[4], xx[4];
    size_t wro[4];
    uint32_t dsw[4];
#pragma unroll
    for (int i = 0; i < 4; i++) {
        const int m = m0 + i * 32 + rsub;
        bb[i] = m / HW;
        const int pos = m % HW;
        yy[i] = pos / W;
        xx[i] = pos % W;
        wro[i] = (size_t)(n0 + i * 32 + rsub) * WROW;
        dsw[i] = SWZ128((uint32_t)((i * 32 + rsub) * 128 + seg * 16));
    }
    const int nlo = t >> 2;      // W_lo row tasks
    const int jlo = t & 3;

    auto fill = [&](int st, int c) {
        const uint32_t stg = sb + (uint32_t)st * STG_SZ;
        const int tap = c / CPT;
        const int cib = (c % CPT) * 32;
        const int dy = tap / 3 - 1, dx = tap % 3 - 1;
        const int ko = tap * CI + cib;
#pragma unroll
        for (int i = 0; i < 4; i++) {
            const int iy = yy[i] + dy, ix = xx[i] + dx;
            const bool ok = (iy >= 0 && iy < H && ix >= 0 && ix < W);
            const unsigned* src = inpk +
                (((size_t)bb[i] * H + (ok ? iy : 0)) * W + (ok ? ix : 0)) * CI +
                cib + seg * 4;
            cp16(stg + dsw[i], src, ok ? 16 : 0);
        }
#pragma unroll
        for (int i = 0; i < 4; i++)
            cp16(stg + 16384 + dsw[i], whh + wro[i] + ko + seg * 4, 16);
#pragma unroll
        for (int i = 0; i < 2; i++) {
            const int n = nlo + i * 64;
            cp16(stg + 40960 + SWZ64((uint32_t)(n * 64 + jlo * 16)),
                 wlo + (size_t)(n0 + n) * WROW + ko + jlo * 8, 16);
        }
    };

    float acc[4][4][4];
#pragma unroll
    for (int a = 0; a < 4; a++)
#pragma unroll
        for (int b = 0; b < 4; b++)
#pragma unroll
            for (int cj = 0; cj < 4; cj++) acc[a][b][cj] = 0.f;

    fill(0, 0);
    CP_COMMIT();
    fill(1, 1);
    CP_COMMIT();

    int st = 0;
    for (int c = 0; c < NCH; c++) {
        CP_WAIT(1);
        __syncthreads();
        const uint32_t stg = sb + (uint32_t)st * STG_SZ;

        // unpack A_hi (low u16 of each packed u32) into stg+32768
#pragma unroll
        for (int i = 0; i < 2; i++) {
            const int task = t + i * 256;
            const int r = task >> 2, j4 = task & 3;
            const uint32_t s1 = stg + SWZ128((uint32_t)(r * 128 + j4 * 32));
            const uint32_t s2 = stg + SWZ128((uint32_t)(r * 128 + j4 * 32 + 16));
            const uint4 u = lds128(s1), v = lds128(s2);
            uint4 o;
            o.x = __byte_perm(u.x, u.y, 0x5410);
            o.y = __byte_perm(u.z, u.w, 0x5410);
            o.z = __byte_perm(v.x, v.y, 0x5410);
            o.w = __byte_perm(v.z, v.w, 0x5410);
            sts128(stg + 32768 + SWZ64((uint32_t)(r * 64 + j4 * 16)), o);
        }
        if (c + 2 < NCH) {
            fill((st + 2) % 3, c + 2);
            CP_COMMIT();
        }
        __syncthreads();

        const uint32_t bApk = stg, bB1 = stg + 16384;
        const uint32_t bAhi = stg + 32768, bWlo = stg + 40960;
        // ---- pass 1: packed virtual-K' (64) x (hi,hi) ----
#pragma unroll
        for (int ks = 0; ks < 4; ks++) {
            const int c0 = ks * 32;
            uint32_t a[4][4];
#pragma unroll
            for (int mt = 0; mt < 4; mt++) {
                const int row = wm * 64 + mt * 16 + (lane & 15);
                ldsm4(a[mt][0], a[mt][1], a[mt][2], a[mt][3],
                      bApk + SWZ128((uint32_t)(row * 128 + c0 + (lane >> 4) * 16)));
            }
            uint32_t b1[8];
#pragma unroll
            for (int p = 0; p < 2; p++) {
                const int row = wn * 32 + p * 16 + (lane & 7) + (lane >> 4) * 8;
                ldsm4(b1[p * 4], b1[p * 4 + 1], b1[p * 4 + 2], b1[p * 4 + 3],
                      bB1 + SWZ128((uint32_t)(row * 128 + c0 + ((lane >> 3) & 1) * 16)));
            }
#pragma unroll
            for (int mt = 0; mt < 4; mt++)
#pragma unroll
                for (int nt = 0; nt < 4; nt++)
                    mma16816(acc[mt][nt], a[mt], &b1[nt * 2]);
        }
        // ---- pass 2: A_hi (real K=32) x W_lo ----
#pragma unroll
        for (int k2 = 0; k2 < 2; k2++) {
            const int c0 = k2 * 32;
            uint32_t a[4][4];
#pragma unroll
            for (int mt = 0; mt < 4; mt++) {
                const int row = wm * 64 + mt * 16 + (lane & 15);
                ldsm4(a[mt][0], a[mt][1], a[mt][2], a[mt][3],
                      bAhi + SWZ64((uint32_t)(row * 64 + c0 + (lane >> 4) * 16)));
            }
            uint32_t bl[8];
#pragma unroll
            for (int p = 0; p < 2; p++) {
                const int row = wn * 32 + p * 16 + (lane & 7) + (lane >> 4) * 8;
                ldsm4(bl[p * 4], bl[p * 4 + 1], bl[p * 4 + 2], bl[p * 4 + 3],
                      bWlo + SWZ64((uint32_t)(row * 64 + c0 + ((lane >> 3) & 1) * 16)));
            }
#pragma unroll
            for (int mt = 0; mt < 4; mt++)
#pragma unroll
                for (int nt = 0; nt < 4; nt++)
                    mma16816(acc[mt][nt], a[mt], &bl[nt * 2]);
        }
        st = (st + 1) % 3;
        __syncthreads();
    }
    CP_WAIT(0);
    __syncthreads();

    // ---- epilogue: bias+relu -> SMEM tile -> 2x2 pool -> out ----
    float* S = (float*)dsm;  // [128][132]
    const int mrow = lane >> 2;
    const int ncol = (lane & 3) * 2;
#pragma unroll
    for (int mt = 0; mt < 4; mt++)
#pragma unroll
        for (int half = 0; half < 2; half++) {
            const int r = wm * 64 + mt * 16 + mrow + half * 8;
#pragma unroll
            for (int nt = 0; nt < 4; nt++)
#pragma unroll
                for (int j = 0; j < 2; j++) {
                    const int ncl = wn * 32 + nt * 8 + ncol + j;
                    float v = acc[mt][nt][half * 2 + j] + bias[n0 + ncl];
                    S[r * 132 + ncl] = v > 0.f ? v : 0.f;
                }
        }
    __syncthreads();

    constexpr int Wo = W / 2;
    constexpr int HWo = HW / 4;
    for (int idx = t; idx < 32 * 128; idx += 256) {
        const int pp = idx >> 7;
        const int cl = idx & 127;
        const int lpy = pp / Wo;
        const int lpx = pp % Wo;
        const int lm = lpy * 2 * W + lpx * 2;
        const int m = m0 + lm;
        const int b = m / HW;
        const int rem = m % HW;
        const int y = rem / W, x = rem % W;
        const float* p = S + lm * 132 + cl;
        float v = fmaxf(fmaxf(p[0], p[132]), fmaxf(p[W * 132], p[(W + 1) * 132]));
        const int pos = (y >> 1) * Wo + (x >> 1);
        if (FEATS) {
            outf[(size_t)b * (CO * HWo) + (size_t)(n0 + cl) * HWo + pos] = v;
        } else {
            __nv_bfloat16 h = __float2bfloat16_rn(v);
            __nv_bfloat16 l = __float2bfloat16_rn(v - __bfloat162float(h));
            unsigned pk = (unsigned)__bfloat16_as_ushort(h) |
                          ((unsigned)__bfloat16_as_ushort(l) << 16);
            outpk[((size_t)b * HWo + pos) * CO + (n0 + cl)] = pk;
        }
    }
}

// ---- weight pack: OIHW -> [co][tap*CI+ci]: whh=(hi,hi) u32, wlo=lo u16 ----
__global__ void wpack_kernel(const float* __restrict__ w,
                             unsigned* __restrict__ ohh,
                             unsigned short* __restrict__ olo, int CO, int CI)
{
    const int i = blockIdx.x * 256 + threadIdx.x;
    if (i >= CO * CI * 9) return;
    const int tap = i % 9;
    const int ci = (i / 9) % CI;
    const int co = i / (9 * CI);
    const float v = w[i];
    const __nv_bfloat16 h = __float2bfloat16_rn(v);
    const __nv_bfloat16 l = __float2bfloat16_rn(v - __bfloat162float(h));
    const unsigned hu = (unsigned)__bfloat16_as_ushort(h);
    const size_t o = (size_t)co * CI * 9 + (size_t)tap * CI + ci;
    ohh[o] = hu | (hu << 16);
    olo[o] = __bfloat16_as_ushort(l);
}

// ---------- conv1: fp32 SIMT (CI=3) with fused pool+pack epilogue ----------
#define CONV1_DSM 68608

__global__ __launch_bounds__(256, 1) void conv1_kernel(
    const float* __restrict__ in, const float* __restrict__ wt,
    const float* __restrict__ bias, unsigned* __restrict__ outpk)
{
    constexpr int CI = 3, H = 64, W = 64, CO = 128;
    constexpr int BK = 27;
    constexpr int HW = H * W;

    extern __shared__ __align__(1024) char dsm[];
    float (*As)[132] = (float(*)[132])dsm;             // [27][132]
    float (*Bs)[132] = (float(*)[132])(dsm + 14784);   // [27][132]

    const int t = threadIdx.x;
    const int m0 = blockIdx.x * 128;
    const int tx = t & 15;
    const int ty = t >> 4;

    float acc[8][8];
#pragma unroll
    for (int i = 0; i < 8; i++)
#pragma unroll
        for (int j = 0; j < 8; j++) acc[i][j] = 0.f;

    // load A (im2col, K=27) and B (weights)
#pragma unroll
    for (int j = 0; j < 14; j++) {
        int e = j * 256 + t;
        if (e >= 27 * 128) break;
        int k = e >> 7;
        int p = e & 127;
        int ci = k / 9;
        int rc = k % 9;
        int s = m0 + p;
        int b = s / HW;
        int rr = s % HW;
        int y = rr / W, x = rr % W;
        int iy = y + rc / 3 - 1;
        int ix = x + rc % 3 - 1;
        float v = 0.f;
        if (iy >= 0 && iy < H && ix >= 0 && ix < W)
            v = in[((size_t)(b * CI + ci) * H + iy) * W + ix];
        As[k][p] = v;
    }
    if (t < 128) {
        const float* wp = wt + (size_t)t * 27;
#pragma unroll
        for (int k = 0; k < 27; k++) Bs[k][t] = wp[k];
    }
    __syncthreads();

#pragma unroll
    for (int kk = 0; kk < BK; kk++) {
        float a[8], bv[8];
        *(float4*)&a[0] = *(const float4*)&As[kk][tx * 8];
        *(float4*)&a[4] = *(const float4*)&As[kk][tx * 8 + 4];
        *(float4*)&bv[0] = *(const float4*)&Bs[kk][ty * 8];
        *(float4*)&bv[4] = *(const float4*)&Bs[kk][ty * 8 + 4];
#pragma unroll
        for (int i = 0; i < 8; i++)
#pragma unroll
            for (int j = 0; j < 8; j++) acc[i][j] += a[i] * bv[j];
    }
    __syncthreads();

    // bias + relu -> staging tile [128][132]
    float* S = (float*)dsm;
#pragma unroll
    for (int i = 0; i < 8; i++) {
        const int r = tx * 8 + i;
#pragma unroll
        for (int j = 0; j < 8; j++) {
            const int cl = ty * 8 + j;
            float v = acc[i][j] + bias[cl];
            S[r * 132 + cl] = v > 0.f ? v : 0.f;
        }
    }
    __syncthreads();

    // pool 2x2 + bf16-split pack -> NHWC u32 (tile = 2 y-rows, y0 even)
    for (int idx = t; idx < 32 * 128; idx += 256) {
        const int pp = idx >> 7;   // 0..31 pooled x
        const int cl = idx & 127;
        const int lm = pp * 2;
        const int m = m0 + lm;
        const int b = m >> 12;
        const int rem = m & 4095;
        const int y = rem >> 6, x = rem & 63;
        const float* p = S + lm * 132 + cl;
        float v = fmaxf(fmaxf(p[0], p[132]), fmaxf(p[64 * 132], p[65 * 132]));
        __nv_bfloat16 h = __float2bfloat16_rn(v);
        __nv_bfloat16 l = __float2bfloat16_rn(v - __bfloat162float(h));
        unsigned pk = (unsigned)__bfloat16_as_ushort(h) |
                      ((unsigned)__bfloat16_as_ushort(l) << 16);
        outpk[((size_t)b * 1024 + (y >> 1) * 32 + (x >> 1)) * 128 + cl] = pk;
    }
}

// ----------------------------- gate logits ---------------------------------
__global__ void gate_logits_kernel(const float* __restrict__ feats,
                                   const float* __restrict__ wg)
{
    int t = blockIdx.x * blockDim.x + threadIdx.x;
    if (t >= BATCH * NEXP) return;
    int b = t >> 4, e = t & 15;
    const float* f = feats + (size_t)b * DFEAT;
    float s = 0.f;
    for (int d = 0; d < DFEAT; d++) s += f[d] * wg[d * NEXP + e];
    g_logits[t] = s;
}

// --------------------------- top-2 + gate softmax --------------------------
__global__ void topk_kernel()
{
    int b = threadIdx.x;
    if (b >= BATCH) return;
    float l[NEXP];
#pragma unroll
    for (int e = 0; e < NEXP; e++) l[e] = g_logits[b * NEXP + e];
    float b1v = -INFINITY, b2v = -INFINITY;
    int b1i = 0, b2i = 0;
#pragma unroll
    for (int e = 0; e < NEXP; e++) {
        float v = l[e];
        if (v > b1v) { b2v = b1v; b2i = b1i; b1v = v; b1i = e; }
        else if (v > b2v) { b2v = v; b2i = e; }
    }
    float e2 = expf(b2v - b1v);
    float denom = 1.f + e2;
    float gate1 = 1.f / denom;
    float gate2 = e2 / denom;
#pragma unroll
    for (int e = 0; e < NEXP; e++) g_gates[b * NEXP + e] = 0.f;
    g_gates[b * NEXP + b1i] = gate1;
    g_gates[b * NEXP + b2i] = gate2;
    g_pairE[2 * b] = b1i;     g_pairG[2 * b] = gate1;
    g_pairE[2 * b + 1] = b2i; g_pairG[2 * b + 1] = gate2;
}

// --------------------- expert-sorted pair permutation ----------------------
__global__ void build_perm_kernel()
{
    __shared__ int scnt[NEXP], soff[NEXP], scur[NEXP];
    int t = threadIdx.x;
    if (t < NEXP) { scnt[t] = 0; scur[t] = 0; }
    __syncthreads();
    atomicAdd(&scnt[g_pairE[t]], 1);
    __syncthreads();
    if (t == 0) {
        int o = 0;
        for (int e = 0; e < NEXP; e++) { soff[e] = o; o += scnt[e]; }
    }
    __syncthreads();
    int e = g_pairE[t];
    int slot = soff[e] + atomicAdd(&scur[e], 1);
    g_perm[slot] = t;
    if (t < NEXP) { g_cnt[t] = scnt[t]; g_off[t] = soff[t]; }
}

// --------------------- grouped expert GEMM (fc1 / fc2) ---------------------
template <int KDIM, int NDIM, bool RELU, bool GATHER>
__global__ __launch_bounds__(256) void expert_gemm_kernel(
    const float* __restrict__ Asrc, const float* __restrict__ Wt,
    const float* __restrict__ bias, float* __restrict__ Out)
{
    const int e = blockIdx.y;
    const int cnt = g_cnt[e];
    const int off = g_off[e];
    const int rbase = blockIdx.z * 32;
    if (rbase >= cnt) return;
    const int n0 = blockIdx.x * 128;
    const int t = threadIdx.x;

    __shared__ __align__(16) float As[32][33];
    __shared__ __align__(16) float Bs[32][128];
    __shared__ int srcRow[32];

    if (t < 32) {
        int rr = rbase + t;
        int sr = -1;
        if (rr < cnt) {
            if (GATHER) sr = g_perm[off + rr] >> 1;
            else        sr = off + rr;
        }
        srcRow[t] = sr;
    }
    __syncthreads();

    float acc[4][4];
#pragma unroll
    for (int i = 0; i < 4; i++)
#pragma unroll
        for (int j = 0; j < 4; j++) acc[i][j] = 0.f;

    const float* wbase = Wt + (size_t)e * KDIM * NDIM + n0;
    const int rg = t >> 5;
    const int cg = t & 31;

    for (int kb = 0; kb < KDIM; kb += 32) {
#pragma unroll
        for (int j = 0; j < 4; j++) {
            int eI = j * 256 + t;
            int row = eI >> 5, k = eI & 31;
            int sr = srcRow[row];
            As[k][row] = (sr >= 0) ? Asrc[(size_t)sr * KDIM + kb + k] : 0.f;
        }
#pragma unroll
        for (int j = 0; j < 16; j++) {
            int eI = j * 256 + t;
            int k = eI >> 7, n = eI & 127;
            Bs[k][n] = wbase[(size_t)(kb + k) * NDIM + n];
        }
        __syncthreads();
#pragma unroll
        for (int kk = 0; kk < 32; kk++) {
            float bv[4];
            *(float4*)&bv[0] = *(const float4*)&Bs[kk][cg * 4];
            float a0 = As[kk][rg * 4 + 0];
            float a1 = As[kk][rg * 4 + 1];
            float a2 = As[kk][rg * 4 + 2];
            float a3 = As[kk][rg * 4 + 3];
#pragma unroll
            for (int j = 0; j < 4; j++) {
                acc[0][j] += a0 * bv[j];
                acc[1][j] += a1 * bv[j];
                acc[2][j] += a2 * bv[j];
                acc[3][j] += a3 * bv[j];
            }
        }
        __syncthreads();
    }
#pragma unroll
    for (int i = 0; i < 4; i++) {
        int rr = rbase + rg * 4 + i;
        if (rr >= cnt) continue;
        int gr = off + rr;
#pragma unroll
        for (int j = 0; j < 4; j++) {
            int n = n0 + cg * 4 + j;
            float v = acc[i][j] + bias[e * NDIM + n];
            if (RELU) v = v > 0.f ? v : 0.f;
            Out[(size_t)gr * NDIM + n] = v;
        }
    }
}

// -------------------------- zero output buffer -----------------------------
__global__ void zero_kernel(float* __restrict__ p, int n)
{
    int i = blockIdx.x * blockDim.x + threadIdx.x;
    if (i < n) p[i] = 0.f;
}

// ------------------- softmax over experts' logits + combine ----------------
__global__ void softmax_combine_kernel(float* __restrict__ y)
{
    const int gr = blockIdx.x;
    const int t = threadIdx.x;
    const int pair = g_perm[gr];
    const int token = pair >> 1;
    const float gate = g_pairG[pair];
    const float* row = g_o + (size_t)gr * OUTD;

    __shared__ float red[256];
    float m = -INFINITY;
    for (int j = t; j < OUTD; j += 256) m = fmaxf(m, row[j]);
    red[t] = m;
    __syncthreads();
    for (int s = 128; s > 0; s >>= 1) {
        if (t < s) red[t] = fmaxf(red[t], red[t + s]);
        __syncthreads();
    }
    const float M = red[0];
    __syncthreads();

    float s = 0.f;
    for (int j = t; j < OUTD; j += 256) s += expf(row[j] - M);
    red[t] = s;
    __syncthreads();
    for (int st = 128; st > 0; st >>= 1) {
        if (t < st) red[t] += red[t + st];
        __syncthreads();
    }
    const float scale = gate / red[0];

    for (int j = t; j < OUTD; j += 256)
        atomicAdd(&y[(size_t)token * OUTD + j], expf(row[j] - M) * scale);
}

// ------------------------------- aux loss ----------------------------------
__global__ void aux_kernel(float* __restrict__ out, int out_size)
{
    __shared__ float imp[NEXP], loadv[NEXP];
    int t = threadIdx.x;
    if (t < NEXP) {
        float s = 0.f, L = 0.f;
        for (int b = 0; b < BATCH; b++) {
            float gv = g_gates[b * NEXP + t];
            s += gv;
            if (gv > 0.f) L += 1.f;
        }
        imp[t] = s;
        loadv[t] = L;
    }
    __syncthreads();
    if (t == 0 && out_size > BATCH * OUTD) {
        float mi = 0.f, ml = 0.f;
        for (int e = 0; e < NEXP; e++) { mi += imp[e]; ml += loadv[e]; }
        mi /= NEXP; ml /= NEXP;
        float vi = 0.f, vl = 0.f;
        for (int e = 0; e < NEXP; e++) {
            float di = imp[e] - mi, dl = loadv[e] - ml;
            vi += di * di; vl += dl * dl;
        }
        vi /= NEXP; vl /= NEXP;
        out[BATCH * OUTD] =
            0.01f * (vi / (mi * mi + 1e-10f) + vl / (ml * ml + 1e-10f));
    }
}

// ------------------------------- launcher ----------------------------------
extern "C" void kernel_launch(void* const* d_in, const int* in_sizes, int n_in,
                              void* d_out, int out_size)
{
    (void)in_sizes; (void)n_in;
    const float* x   = (const float*)d_in[0];
    const float* cw1 = (const float*)d_in[1];
    const float* cb1 = (const float*)d_in[2];
    const float* cw2 = (const float*)d_in[3];
    const float* cb2 = (const float*)d_in[4];
    const float* cw3 = (const float*)d_in[5];
    const float* cb3 = (const float*)d_in[6];
    const float* cw4 = (const float*)d_in[7];
    const float* cb4 = (const float*)d_in[8];
    const float* cw5 = (const float*)d_in[9];
    const float* cb5 = (const float*)d_in[10];
    const float* w1  = (const float*)d_in[11];
    const float* b1  = (const float*)d_in[12];
    const float* w2  = (const float*)d_in[13];
    const float* b2  = (const float*)d_in[14];
    const float* wg  = (const float*)d_in[15];
    float* y = (float*)d_out;

    float *pool_s, *h_s, *o_s;
    unsigned *pkA, *pkB, *whh;
    unsigned short* wlo;
    cudaGetSymbolAddress((void**)&pool_s, g_pool);
    cudaGetSymbolAddress((void**)&h_s, g_h);
    cudaGetSymbolAddress((void**)&o_s, g_o);
    cudaGetSymbolAddress((void**)&pkA, g_pkA);
    cudaGetSymbolAddress((void**)&pkB, g_pkB);
    cudaGetSymbolAddress((void**)&whh, g_whh);
    cudaGetSymbolAddress((void**)&wlo, g_wlo);

    cudaFuncSetAttribute(conv1_kernel,
                         cudaFuncAttributeMaxDynamicSharedMemorySize, CONV1_DSM);
    cudaFuncSetAttribute(conv_mma_kernel<128, 32, 32, 256, false>,
                         cudaFuncAttributeMaxDynamicSharedMemorySize, CONV_DSM);
    cudaFuncSetAttribute(conv_mma_kernel<256, 16, 16, 256, false>,
                         cudaFuncAttributeMaxDynamicSharedMemorySize, CONV_DSM);
    cudaFuncSetAttribute(conv_mma_kernel<256, 8, 8, 512, false>,
                         cudaFuncAttributeMaxDynamicSharedMemorySize, CONV_DSM);
    cudaFuncSetAttribute(conv_mma_kernel<512, 4, 4, 512, true>,
                         cudaFuncAttributeMaxDynamicSharedMemorySize, CONV_DSM);

    // ---- L1: fp32 SIMT conv + fused pool/pack -> pkA ----
    conv1_kernel<<<8192, 256, CONV1_DSM>>>(x, cw1, cb1, pkA);

    // ---- L2: 128 -> 256 @32x32, out pooled packed -> pkB ----
    wpack_kernel<<<(256 * 128 * 9 + 255) / 256, 256>>>(cw2, whh, wlo, 256, 128);
    conv_mma_kernel<128, 32, 32, 256, false>
        <<<dim3(2048, 2), 256, CONV_DSM>>>(pkA, whh, wlo, cb2, pkB, nullptr);

    // ---- L3: 256 -> 256 @16x16 -> pkA ----
    wpack_kernel<<<(256 * 256 * 9 + 255) / 256, 256>>>(cw3, whh, wlo, 256, 256);
    conv_mma_kernel<256, 16, 16, 256, false>
        <<<dim3(512, 2), 256, CONV_DSM>>>(pkB, whh, wlo, cb3, pkA, nullptr);

    // ---- L4: 256 -> 512 @8x8 -> pkB ----
    wpack_kernel<<<(512 * 256 * 9 + 255) / 256, 256>>>(cw4, whh, wlo, 512, 256);
    conv_mma_kernel<256, 8, 8, 512, false>
        <<<dim3(128, 4), 256, CONV_DSM>>>(pkA, whh, wlo, cb4, pkB, nullptr);

    // ---- L5: 512 -> 512 @4x4 -> feats fp32 ----
    wpack_kernel<<<(512 * 512 * 9 + 255) / 256, 256>>>(cw5, whh, wlo, 512, 512);
    conv_mma_kernel<512, 4, 4, 512, true>
        <<<dim3(32, 4), 256, CONV_DSM>>>(pkB, whh, wlo, cb5, nullptr, pool_s);

    // ---- gating ----
    gate_logits_kernel<<<NEXP, 256>>>(pool_s, wg);
    topk_kernel<<<1, 256>>>();
    build_perm_kernel<<<1, 512>>>();

    // ---- sparse expert MLPs (512 active pairs) ----
    expert_gemm_kernel<DFEAT, HID, true, true>
        <<<dim3(HID / 128, NEXP, 8), 256>>>(pool_s, w1, b1, h_s);
    expert_gemm_kernel<HID, OUTD, false, false>
        <<<dim3(OUTD / 128, NEXP, 8), 256>>>(h_s, w2, b2, o_s);

    // ---- combine + aux ----
    zero_kernel<<<(out_size + 255) / 256, 256>>>(y, out_size);
    softmax_combine_kernel<<<NPAIR, 256>>>(y);
    aux_kernel<<<1, 256>>>(y, out_size);
}

// round 5
// speedup vs baseline: 3.0688x; 1.0433x over previous
#include <cuda_runtime.h>
#include <cuda_bf16.h>
#include <math.h>
#include <stdint.h>

// ---------------------------------------------------------------------------
// ToyMoE: conv stack (5x conv3x3+relu+maxpool2) -> top-2 gating (eval)
//         -> sparse top-2 expert MLPs -> softmax -> gated combine + aux loss
// conv2-5 AND expert MLPs on bf16 mma.sync with 3-term split
// (hi*hi + lo*hi + hi*lo => fp32-class accuracy). Fused pool/pack epilogues.
// ---------------------------------------------------------------------------

#define BATCH 256
#define DFEAT 2048
#define HID 4096
#define OUTD 1024
#define NEXP 16
#define NPAIR (BATCH * 2)

template <int X> struct LG { static constexpr int v = 1 + LG<X / 2>::v; };
template <> struct LG<1> { static constexpr int v = 0; };

// ------------------------- scratch (device globals) ------------------------
__device__ unsigned       g_pkA[(size_t)256 * 1024 * 128]; // packed acts (L1/L3 out)
__device__ unsigned short g_hiA[(size_t)256 * 1024 * 128]; // hi-only acts
__device__ unsigned       g_pkB[(size_t)256 * 256 * 256];  // packed acts (L2/L4 out)
__device__ unsigned short g_hiB[(size_t)256 * 256 * 256];
__device__ unsigned       g_whh[4423680];                  // conv weights (hi,hi)
__device__ unsigned short g_wlo[4423680];                  // conv weights lo
__device__ float          g_pool[BATCH * DFEAT];           // feats fp32 (gating)
__device__ unsigned       g_featpk[BATCH * DFEAT];
__device__ unsigned short g_feathi[BATCH * DFEAT];
__device__ unsigned       g_hpk[(size_t)NPAIR * HID];
__device__ unsigned short g_hhi[(size_t)NPAIR * HID];
__device__ float          g_logits[BATCH * NEXP];
__device__ float          g_gates[BATCH * NEXP];
__device__ int            g_pairE[NPAIR];
__device__ float          g_pairG[NPAIR];
__device__ int            g_perm[NPAIR];
__device__ int            g_cnt[NEXP];
__device__ int            g_off[NEXP];
__device__ float          g_o[(size_t)NPAIR * OUTD];

// ------------------------------ PTX helpers --------------------------------
__device__ __forceinline__ uint32_t smem_u32(const void* p) {
    uint32_t a;
    asm("{ .reg .u64 t; cvta.to.shared.u64 t, %1; cvt.u32.u64 %0, t; }"
        : "=r"(a) : "l"(p));
    return a;
}

#define SWZ128(x) ((x) ^ (((x) >> 3) & 0x70))
#define SWZ64(x)  ((x) ^ (((x) >> 3) & 0x30))

__device__ __forceinline__ void cp16(uint32_t dst, const void* src, int sz) {
    asm volatile("cp.async.cg.shared.global [%0], [%1], 16, %2;"
                 :: "r"(dst), "l"(src), "r"(sz) : "memory");
}
#define CP_COMMIT() asm volatile("cp.async.commit_group;" ::: "memory")
#define CP_WAIT(n)  asm volatile("cp.async.wait_group %0;" :: "n"(n) : "memory")

__device__ __forceinline__ void ldsm4(uint32_t& r0, uint32_t& r1,
                                      uint32_t& r2, uint32_t& r3, uint32_t a) {
    asm volatile("ldmatrix.sync.aligned.m8n8.x4.shared.b16 {%0,%1,%2,%3}, [%4];"
                 : "=r"(r0), "=r"(r1), "=r"(r2), "=r"(r3) : "r"(a));
}
__device__ __forceinline__ void mma16816(float* d, const uint32_t* a,
                                         const uint32_t* b) {
    asm volatile(
        "mma.sync.aligned.m16n8k16.row.col.f32.bf16.bf16.f32 "
        "{%0,%1,%2,%3}, {%4,%5,%6,%7}, {%8,%9}, {%0,%1,%2,%3};"
        : "+f"(d[0]), "+f"(d[1]), "+f"(d[2]), "+f"(d[3])
        : "r"(a[0]), "r"(a[1]), "r"(a[2]), "r"(a[3]), "r"(b[0]), "r"(b[1]));
}
__device__ __forceinline__ unsigned packsplit(float v, unsigned short* hi_out) {
    __nv_bfloat16 h = __float2bfloat16_rn(v);
    __nv_bfloat16 l = __float2bfloat16_rn(v - __bfloat162float(h));
    unsigned hu = (unsigned)__bfloat16_as_ushort(h);
    *hi_out = (unsigned short)hu;
    return hu | ((unsigned)__bfloat16_as_ushort(l) << 16);
}

// --------------------- bf16 mma.sync conv3x3 (SAME, relu, fused pool) ------
// Pass1 (virtual K'=64): A_pk (packed hi|lo) x Whh=(hi,hi) => hi*hi + lo*hi
// Pass2 (real K=32):     A_hi (raw cp.async)  x W_lo       => hi*lo
// 3-stage cp.async pipeline, ONE barrier per chunk.
#define STG_SZ 49152
#define CONV_DSM (3 * STG_SZ + 1024)

template <int CI, int H, int W, int CO, bool FEATS>
__global__ __launch_bounds__(256, 1) void conv_mma_kernel(
    const unsigned* __restrict__ inpk, const unsigned short* __restrict__ inhi,
    const unsigned* __restrict__ whh, const unsigned short* __restrict__ wlo,
    const float* __restrict__ bias,
    unsigned* __restrict__ outpk, unsigned short* __restrict__ outhi,
    float* __restrict__ outf)
{
    constexpr int HW = H * W;
    constexpr int LHW = LG<HW>::v;
    constexpr int LW = LG<W>::v;
    constexpr int CPT = CI / 32;
    constexpr int NCH = 9 * CPT;
    constexpr int WROW = 9 * CI;

    extern __shared__ __align__(1024) char dsm[];
    const uint32_t sb = smem_u32(dsm);
    const int t = threadIdx.x;
    const int lane = t & 31;
    const int wid = t >> 5;
    const int wm = wid & 1, wn = wid >> 1;
    const int m0 = blockIdx.x * 128, n0 = blockIdx.y * 128;
    const int seg = t & 7;
    const int rsub = t >> 3;

    int yy[4], xx[4];
    int bb[4];
    size_t wro[4];
    uint32_t dsw[4];
#pragma unroll
    for (int i = 0; i < 4; i++) {
        const int m = m0 + i * 32 + rsub;
        bb[i] = m >> LHW;
        const int pos = m & (HW - 1);
        yy[i] = pos >> LW;
        xx[i] = pos & (W - 1);
        wro[i] = (size_t)(n0 + i * 32 + rsub) * WROW;
        dsw[i] = SWZ128((uint32_t)((i * 32 + rsub) * 128 + seg * 16));
    }
    const int nlo = t >> 2;
    const int jlo = t & 3;

    auto fill = [&](int st, int c) {
        const uint32_t stg = sb + (uint32_t)st * STG_SZ;
        const int tap = c / CPT;
        const int cib = (c % CPT) * 32;
        const int dy = tap / 3 - 1, dx = tap % 3 - 1;
        const int ko = tap * CI + cib;
#pragma unroll
        for (int i = 0; i < 4; i++) {
            const int iy = yy[i] + dy, ix = xx[i] + dx;
            const bool ok = (iy >= 0 && iy < H && ix >= 0 && ix < W);
            cp16(stg + dsw[i],
                 inpk + (((size_t)bb[i] * H + (ok ? iy : 0)) * W + (ok ? ix : 0)) * CI +
                     cib + seg * 4,
                 ok ? 16 : 0);
        }
#pragma unroll
        for (int i = 0; i < 4; i++)
            cp16(stg + 16384 + dsw[i], whh + wro[i] + ko + seg * 4, 16);
        // A_hi: 128 rows x 64B (raw copy of hi-only activations)
#pragma unroll
        for (int i = 0; i < 2; i++) {
            const int task = t + i * 256;
            const int r = task >> 2, sg = task & 3;
            const int m = m0 + r;
            const int bI = m >> LHW;
            const int rem = m & (HW - 1);
            const int iy = (rem >> LW) + dy;
            const int ix = (rem & (W - 1)) + dx;
            const bool ok = (iy >= 0 && iy < H && ix >= 0 && ix < W);
            cp16(stg + 32768 + SWZ64((uint32_t)(r * 64 + sg * 16)),
                 inhi + (((size_t)bI * H + (ok ? iy : 0)) * W + (ok ? ix : 0)) * CI +
                     cib + sg * 8,
                 ok ? 16 : 0);
        }
#pragma unroll
        for (int i = 0; i < 2; i++) {
            const int n = nlo + i * 64;
            cp16(stg + 40960 + SWZ64((uint32_t)(n * 64 + jlo * 16)),
                 wlo + (size_t)(n0 + n) * WROW + ko + jlo * 8, 16);
        }
    };

    float acc[4][4][4];
#pragma unroll
    for (int a = 0; a < 4; a++)
#pragma unroll
        for (int b = 0; b < 4; b++)
#pragma unroll
            for (int cj = 0; cj < 4; cj++) acc[a][b][cj] = 0.f;

    fill(0, 0);
    CP_COMMIT();
    fill(1, 1);
    CP_COMMIT();

    int st = 0;
    for (int c = 0; c < NCH; c++) {
        if (c + 1 < NCH) { CP_WAIT(1); } else { CP_WAIT(0); }
        __syncthreads();
        if (c + 2 < NCH) {
            fill(st >= 1 ? st - 1 : st + 2, c + 2);
            CP_COMMIT();
        }
        const uint32_t stg = sb + (uint32_t)st * STG_SZ;
        const uint32_t bApk = stg, bB1 = stg + 16384;
        const uint32_t bAhi = stg + 32768, bWlo = stg + 40960;
#pragma unroll
        for (int ks = 0; ks < 4; ks++) {
            const int c0 = ks * 32;
            uint32_t a[4][4];
#pragma unroll
            for (int mt = 0; mt < 4; mt++) {
                const int row = wm * 64 + mt * 16 + (lane & 15);
                ldsm4(a[mt][0], a[mt][1], a[mt][2], a[mt][3],
                      bApk + SWZ128((uint32_t)(row * 128 + c0 + (lane >> 4) * 16)));
            }
            uint32_t b1[8];
#pragma unroll
            for (int p = 0; p < 2; p++) {
                const int row = wn * 32 + p * 16 + (lane & 7) + (lane >> 4) * 8;
                ldsm4(b1[p * 4], b1[p * 4 + 1], b1[p * 4 + 2], b1[p * 4 + 3],
                      bB1 + SWZ128((uint32_t)(row * 128 + c0 + ((lane >> 3) & 1) * 16)));
            }
#pragma unroll
            for (int mt = 0; mt < 4; mt++)
#pragma unroll
                for (int nt = 0; nt < 4; nt++)
                    mma16816(acc[mt][nt], a[mt], &b1[nt * 2]);
        }
#pragma unroll
        for (int k2 = 0; k2 < 2; k2++) {
            const int c0 = k2 * 32;
            uint32_t a[4][4];
#pragma unroll
            for (int mt = 0; mt < 4; mt++) {
                const int row = wm * 64 + mt * 16 + (lane & 15);
                ldsm4(a[mt][0], a[mt][1], a[mt][2], a[mt][3],
                      bAhi + SWZ64((uint32_t)(row * 64 + c0 + (lane >> 4) * 16)));
            }
            uint32_t bl[8];
#pragma unroll
            for (int p = 0; p < 2; p++) {
                const int row = wn * 32 + p * 16 + (lane & 7) + (lane >> 4) * 8;
                ldsm4(bl[p * 4], bl[p * 4 + 1], bl[p * 4 + 2], bl[p * 4 + 3],
                      bWlo + SWZ64((uint32_t)(row * 64 + c0 + ((lane >> 3) & 1) * 16)));
            }
#pragma unroll
            for (int mt = 0; mt < 4; mt++)
#pragma unroll
                for (int nt = 0; nt < 4; nt++)
                    mma16816(acc[mt][nt], a[mt], &bl[nt * 2]);
        }
        st = (st + 1 == 3) ? 0 : st + 1;
    }
    __syncthreads();

    // ---- epilogue: bias+relu -> SMEM tile -> 2x2 pool -> packed outputs ----
    float* S = (float*)dsm;  // [128][132]
    const int mrow = lane >> 2;
    const int ncol = (lane & 3) * 2;
#pragma unroll
    for (int mt = 0; mt < 4; mt++)
#pragma unroll
        for (int half = 0; half < 2; half++) {
            const int r = wm * 64 + mt * 16 + mrow + half * 8;
#pragma unroll
            for (int nt = 0; nt < 4; nt++)
#pragma unroll
                for (int j = 0; j < 2; j++) {
                    const int ncl = wn * 32 + nt * 8 + ncol + j;
                    float v = acc[mt][nt][half * 2 + j] + bias[n0 + ncl];
                    S[r * 132 + ncl] = v > 0.f ? v : 0.f;
                }
        }
    __syncthreads();

    constexpr int Wo = W / 2;
    constexpr int HWo = HW / 4;
    for (int idx = t; idx < 32 * 128; idx += 256) {
        const int pp = idx >> 7;
        const int cl = idx & 127;
        const int lpy = pp / Wo;
        const int lpx = pp % Wo;
        const int lm = lpy * 2 * W + lpx * 2;
        const int m = m0 + lm;
        const int b = m >> LHW;
        const int rem = m & (HW - 1);
        const int y = rem >> LW, x = rem & (W - 1);
        const float* p = S + lm * 132 + cl;
        float v = fmaxf(fmaxf(p[0], p[132]), fmaxf(p[W * 132], p[(W + 1) * 132]));
        const int pos = (y >> 1) * Wo + (x >> 1);
        unsigned short hib;
        unsigned pk = packsplit(v, &hib);
        if (FEATS) {
            const int d = (n0 + cl) * HWo + pos;
            outf[(size_t)b * DFEAT + d] = v;
            outpk[(size_t)b * DFEAT + d] = pk;
            outhi[(size_t)b * DFEAT + d] = hib;
        } else {
            const size_t oi = ((size_t)b * HWo + pos) * CO + (n0 + cl);
            outpk[oi] = pk;
            outhi[oi] = hib;
        }
    }
}

// ---- weight pack: OIHW -> [co][tap*CI+ci]: whh=(hi,hi) u32, wlo=lo u16 ----
__global__ void wpack_kernel(const float* __restrict__ w,
                             unsigned* __restrict__ ohh,
                             unsigned short* __restrict__ olo, int CO, int CI)
{
    const int i = blockIdx.x * 256 + threadIdx.x;
    if (i >= CO * CI * 9) return;
    const int tap = i % 9;
    const int ci = (i / 9) % CI;
    const int co = i / (9 * CI);
    const float v = w[i];
    const __nv_bfloat16 h = __float2bfloat16_rn(v);
    const __nv_bfloat16 l = __float2bfloat16_rn(v - __bfloat162float(h));
    const unsigned hu = (unsigned)__bfloat16_as_ushort(h);
    const size_t o = (size_t)co * CI * 9 + (size_t)tap * CI + ci;
    ohh[o] = hu | (hu << 16);
    olo[o] = __bfloat16_as_ushort(l);
}

// -------------- grouped expert GEMM, bf16 mma (fc1 / fc2) ------------------
// M-tile 32 rows x N-tile 128, chunk = 32 real k. W converted fp32->bf16
// in-kernel into the conv kernel's exact SW128/SW64 n-major layouts.
#define ESTG 47104
#define EXP_DSM (3 * ESTG + 1024)

template <int KDIM, int NDIM, bool RELU, bool GATHER, bool PACKOUT>
__global__ __launch_bounds__(256, 1) void expert_mma_kernel(
    const unsigned* __restrict__ Apk, const unsigned short* __restrict__ Ahi,
    const float* __restrict__ Wt, const float* __restrict__ bias,
    unsigned* __restrict__ opk, unsigned short* __restrict__ ohi,
    float* __restrict__ of)
{
    constexpr int NCH = KDIM / 32;
    const int e = blockIdx.y;
    const int cnt = g_cnt[e];
    const int off = g_off[e];
    const int rbase = blockIdx.z * 32;
    if (rbase >= cnt) return;
    const int n0 = blockIdx.x * 128;

    extern __shared__ __align__(1024) char dsm[];
    const uint32_t sb = smem_u32(dsm);
    const int t = threadIdx.x;
    const int lane = t & 31;
    const int wn = t >> 5;

    int* srcRow = (int*)(dsm + 3 * ESTG);
    if (t < 32) {
        int rr = rbase + t, sr = -1;
        if (rr < cnt) sr = GATHER ? (g_perm[off + rr] >> 1) : (off + rr);
        srcRow[t] = sr;
    }
    __syncthreads();

    const float* wbase = Wt + (size_t)e * KDIM * NDIM + n0;

    auto fill = [&](int st, int c) {
        const uint32_t stg = sb + (uint32_t)st * ESTG;
        const int kb = c * 32;
        {
            const int r = t >> 3, sg = t & 7;
            const int sr = srcRow[r];
            cp16(stg + SWZ128((uint32_t)(r * 128 + sg * 16)),
                 Apk + ((sr < 0) ? 0 : ((size_t)sr * KDIM + kb + sg * 4)),
                 sr < 0 ? 0 : 16);
        }
        if (t < 128) {
            const int r = t >> 2, sg = t & 3;
            const int sr = srcRow[r];
            cp16(stg + 4096 + SWZ64((uint32_t)(r * 64 + sg * 16)),
                 Ahi + ((sr < 0) ? 0 : ((size_t)sr * KDIM + kb + sg * 8)),
                 sr < 0 ? 0 : 16);
        }
#pragma unroll
        for (int i = 0; i < 4; i++) {
            const int task = t + i * 256;
            const int k = task >> 5, sg = task & 31;
            cp16(stg + 6144 + (uint32_t)(k * 512 + sg * 16),
                 wbase + (size_t)(kb + k) * NDIM + sg * 4, 16);
        }
    };

    float acc[2][2][4];
#pragma unroll
    for (int a = 0; a < 2; a++)
#pragma unroll
        for (int b = 0; b < 2; b++)
#pragma unroll
            for (int cj = 0; cj < 4; cj++) acc[a][b][cj] = 0.f;

    fill(0, 0);
    CP_COMMIT();
    fill(1, 1);
    CP_COMMIT();

    int st = 0;
    for (int c = 0; c < NCH; c++) {
        if (c + 1 < NCH) { CP_WAIT(1); } else { CP_WAIT(0); }
        __syncthreads();
        if (c + 2 < NCH) {
            fill(st >= 1 ? st - 1 : st + 2, c + 2);
            CP_COMMIT();
        }
        char* stgc = dsm + (size_t)st * ESTG;
        // ---- convert W fp32 tile -> Whh (SW128) + Wlo (SW64) ----
        {
            const int k = t >> 3, ng = t & 7;
#pragma unroll
            for (int j = 0; j < 4; j++) {
                const float4 w =
                    *(const float4*)(stgc + 6144 + k * 512 + ng * 64 + j * 16);
                const float vv[4] = {w.x, w.y, w.z, w.w};
#pragma unroll
                for (int jj = 0; jj < 4; jj++) {
                    const int n = ng * 16 + j * 4 + jj;
                    unsigned short hib;
                    unsigned pk = packsplit(vv[jj], &hib);
                    unsigned hu = pk & 0xFFFFu;
                    *(unsigned*)(stgc + 22528 +
                                 SWZ128((uint32_t)(n * 128 + 4 * k))) =
                        hu | (hu << 16);
                    *(unsigned short*)(stgc + 38912 +
                                       SWZ64((uint32_t)(n * 64 + 2 * k))) =
                        (unsigned short)(pk >> 16);
                }
            }
        }
        __syncthreads();

        const uint32_t stg = sb + (uint32_t)st * ESTG;
        const uint32_t bApk = stg, bAhi = stg + 4096;
        const uint32_t bWhh = stg + 22528, bWlo = stg + 38912;
#pragma unroll
        for (int ks = 0; ks < 4; ks++) {
            const int c0 = ks * 32;
            uint32_t a[2][4];
#pragma unroll
            for (int mt = 0; mt < 2; mt++) {
                const int row = mt * 16 + (lane & 15);
                ldsm4(a[mt][0], a[mt][1], a[mt][2], a[mt][3],
                      bApk + SWZ128((uint32_t)(row * 128 + c0 + (lane >> 4) * 16)));
            }
            uint32_t b1[4];
            {
                const int row = wn * 16 + (lane & 7) + (lane >> 4) * 8;
                ldsm4(b1[0], b1[1], b1[2], b1[3],
                      bWhh + SWZ128((uint32_t)(row * 128 + c0 + ((lane >> 3) & 1) * 16)));
            }
#pragma unroll
            for (int mt = 0; mt < 2; mt++) {
                mma16816(acc[mt][0], a[mt], &b1[0]);
                mma16816(acc[mt][1], a[mt], &b1[2]);
            }
        }
#pragma unroll
        for (int k2 = 0; k2 < 2; k2++) {
            const int c0 = k2 * 32;
            uint32_t a[2][4];
#pragma unroll
            for (int mt = 0; mt < 2; mt++) {
                const int row = mt * 16 + (lane & 15);
                ldsm4(a[mt][0], a[mt][1], a[mt][2], a[mt][3],
                      bAhi + SWZ64((uint32_t)(row * 64 + c0 + (lane >> 4) * 16)));
            }
            uint32_t bl[4];
            {
                const int row = wn * 16 + (lane & 7) + (lane >> 4) * 8;
                ldsm4(bl[0], bl[1], bl[2], bl[3],
                      bWlo + SWZ64((uint32_t)(row * 64 + c0 + ((lane >> 3) & 1) * 16)));
            }
#pragma unroll
            for (int mt = 0; mt < 2; mt++) {
                mma16816(acc[mt][0], a[mt], &bl[0]);
                mma16816(acc[mt][1], a[mt], &bl[2]);
            }
        }
        st = (st + 1 == 3) ? 0 : st + 1;
    }

    // ---- epilogue ----
#pragma unroll
    for (int mt = 0; mt < 2; mt++)
#pragma unroll
        for (int half = 0; half < 2; half++) {
            const int rr = rbase + mt * 16 + (lane >> 2) + half * 8;
            if (rr >= cnt) continue;
            const int gr = off + rr;
#pragma unroll
            for (int nt = 0; nt < 2; nt++)
#pragma unroll
                for (int j = 0; j < 2; j++) {
                    const int n = n0 + wn * 16 + nt * 8 + (lane & 3) * 2 + j;
                    float v = acc[mt][nt][half * 2 + j] + bias[(size_t)e * NDIM + n];
                    if (RELU) v = v > 0.f ? v : 0.f;
                    if (PACKOUT) {
                        unsigned short hib;
                        unsigned pk = packsplit(v, &hib);
                        opk[(size_t)gr * NDIM + n] = pk;
                        ohi[(size_t)gr * NDIM + n] = hib;
                    } else {
                        of[(size_t)gr * NDIM + n] = v;
                    }
                }
        }
}

// ---------- conv1: fp32 SIMT (CI=3) with fused pool+pack epilogue ----------
#define CONV1_DSM 68608

__global__ __launch_bounds__(256, 1) void conv1_kernel(
    const float* __restrict__ in, const float* __restrict__ wt,
    const float* __restrict__ bias, unsigned* __restrict__ outpk,
    unsigned short* __restrict__ outhi)
{
    constexpr int CI = 3, H = 64, W = 64;
    constexpr int BK = 27;
    constexpr int HW = H * W;

    extern __shared__ __align__(1024) char dsm[];
    float (*As)[132] = (float(*)[132])dsm;
    float (*Bs)[132] = (float(*)[132])(dsm + 14784);

    const int t = threadIdx.x;
    const int m0 = blockIdx.x * 128;
    const int tx = t & 15;
    const int ty = t >> 4;

    float acc[8][8];
#pragma unroll
    for (int i = 0; i < 8; i++)
#pragma unroll
        for (int j = 0; j < 8; j++) acc[i][j] = 0.f;

#pragma unroll
    for (int j = 0; j < 14; j++) {
        int e = j * 256 + t;
        if (e >= 27 * 128) break;
        int k = e >> 7;
        int p = e & 127;
        int ci = k / 9;
        int rc = k % 9;
        int s = m0 + p;
        int b = s / HW;
        int rr = s % HW;
        int y = rr / W, x = rr % W;
        int iy = y + rc / 3 - 1;
        int ix = x + rc % 3 - 1;
        float v = 0.f;
        if (iy >= 0 && iy < H && ix >= 0 && ix < W)
            v = in[((size_t)(b * CI + ci) * H + iy) * W + ix];
        As[k][p] = v;
    }
    if (t < 128) {
        const float* wp = wt + (size_t)t * 27;
#pragma unroll
        for (int k = 0; k < 27; k++) Bs[k][t] = wp[k];
    }
    __syncthreads();

#pragma unroll
    for (int kk = 0; kk < BK; kk++) {
        float a[8], bv[8];
        *(float4*)&a[0] = *(const float4*)&As[kk][tx * 8];
        *(float4*)&a[4] = *(const float4*)&As[kk][tx * 8 + 4];
        *(float4*)&bv[0] = *(const float4*)&Bs[kk][ty * 8];
        *(float4*)&bv[4] = *(const float4*)&Bs[kk][ty * 8 + 4];
#pragma unroll
        for (int i = 0; i < 8; i++)
#pragma unroll
            for (int j = 0; j < 8; j++) acc[i][j] += a[i] * bv[j];
    }
    __syncthreads();

    float* S = (float*)dsm;
#pragma unroll
    for (int i = 0; i < 8; i++) {
        const int r = tx * 8 + i;
#pragma unroll
        for (int j = 0; j < 8; j++) {
            const int cl = ty * 8 + j;
            float v = acc[i][j] + bias[cl];
            S[r * 132 + cl] = v > 0.f ? v : 0.f;
        }
    }
    __syncthreads();

    for (int idx = t; idx < 32 * 128; idx += 256) {
        const int pp = idx >> 7;
        const int cl = idx & 127;
        const int lm = pp * 2;
        const int m = m0 + lm;
        const int b = m >> 12;
        const int rem = m & 4095;
        const int y = rem >> 6, x = rem & 63;
        const float* p = S + lm * 132 + cl;
        float v = fmaxf(fmaxf(p[0], p[132]), fmaxf(p[64 * 132], p[65 * 132]));
        unsigned short hib;
        unsigned pk = packsplit(v, &hib);
        const size_t oi = ((size_t)b * 1024 + (y >> 1) * 32 + (x >> 1)) * 128 + cl;
        outpk[oi] = pk;
        outhi[oi] = hib;
    }
}

// ----------------------------- gate logits ---------------------------------
__global__ void gate_logits_kernel(const float* __restrict__ feats,
                                   const float* __restrict__ wg)
{
    int t = blockIdx.x * blockDim.x + threadIdx.x;
    if (t >= BATCH * NEXP) return;
    int b = t >> 4, e = t & 15;
    const float* f = feats + (size_t)b * DFEAT;
    float s = 0.f;
    for (int d = 0; d < DFEAT; d++) s += f[d] * wg[d * NEXP + e];
    g_logits[t] = s;
}

// ------------------- top-2 + gate softmax + perm (fused) -------------------
__global__ void topk_perm_kernel()
{
    __shared__ int scnt[NEXP], soff[NEXP], scur[NEXP];
    const int t = threadIdx.x;  // 512
    if (t < BATCH) {
        const int b = t;
        float l[NEXP];
#pragma unroll
        for (int e = 0; e < NEXP; e++) l[e] = g_logits[b * NEXP + e];
        float b1v = -INFINITY, b2v = -INFINITY;
        int b1i = 0, b2i = 0;
#pragma unroll
        for (int e = 0; e < NEXP; e++) {
            float v = l[e];
            if (v > b1v) { b2v = b1v; b2i = b1i; b1v = v; b1i = e; }
            else if (v > b2v) { b2v = v; b2i = e; }
        }
        float e2 = expf(b2v - b1v);
        float denom = 1.f + e2;
        float gate1 = 1.f / denom;
        float gate2 = e2 / denom;
#pragma unroll
        for (int e = 0; e < NEXP; e++) g_gates[b * NEXP + e] = 0.f;
        g_gates[b * NEXP + b1i] = gate1;
        g_gates[b * NEXP + b2i] = gate2;
        g_pairE[2 * b] = b1i;     g_pairG[2 * b] = gate1;
        g_pairE[2 * b + 1] = b2i; g_pairG[2 * b + 1] = gate2;
    }
    if (t < NEXP) { scnt[t] = 0; scur[t] = 0; }
    __syncthreads();
    const int e = g_pairE[t];
    atomicAdd(&scnt[e], 1);
    __syncthreads();
    if (t == 0) {
        int o = 0;
        for (int i = 0; i < NEXP; i++) { soff[i] = o; o += scnt[i]; }
    }
    __syncthreads();
    const int slot = soff[e] + atomicAdd(&scur[e], 1);
    g_perm[slot] = t;
    if (t < NEXP) { g_cnt[t] = scnt[t]; g_off[t] = soff[t]; }
}

// -------------------------- zero output buffer -----------------------------
__global__ void zero_kernel(float* __restrict__ p, int n)
{
    int i = blockIdx.x * blockDim.x + threadIdx.x;
    if (i < n) p[i] = 0.f;
}

// ------------------- softmax over experts' logits + combine ----------------
__global__ void softmax_combine_kernel(float* __restrict__ y)
{
    const int gr = blockIdx.x;
    const int t = threadIdx.x;
    const int pair = g_perm[gr];
    const int token = pair >> 1;
    const float gate = g_pairG[pair];
    const float* row = g_o + (size_t)gr * OUTD;

    __shared__ float red[256];
    float m = -INFINITY;
    for (int j = t; j < OUTD; j += 256) m = fmaxf(m, row[j]);
    red[t] = m;
    __syncthreads();
    for (int s = 128; s > 0; s >>= 1) {
        if (t < s) red[t] = fmaxf(red[t], red[t + s]);
        __syncthreads();
    }
    const float M = red[0];
    __syncthreads();

    float s = 0.f;
    for (int j = t; j < OUTD; j += 256) s += expf(row[j] - M);
    red[t] = s;
    __syncthreads();
    for (int st = 128; st > 0; st >>= 1) {
        if (t < st) red[t] += red[t + st];
        __syncthreads();
    }
    const float scale = gate / red[0];

    for (int j = t; j < OUTD; j += 256)
        atomicAdd(&y[(size_t)token * OUTD + j], expf(row[j] - M) * scale);
}

// ------------------------------- aux loss ----------------------------------
__global__ void aux_kernel(float* __restrict__ out, int out_size)
{
    __shared__ float imp[NEXP], loadv[NEXP];
    int t = threadIdx.x;
    if (t < NEXP) {
        float s = 0.f, L = 0.f;
        for (int b = 0; b < BATCH; b++) {
            float gv = g_gates[b * NEXP + t];
            s += gv;
            if (gv > 0.f) L += 1.f;
        }
        imp[t] = s;
        loadv[t] = L;
    }
    __syncthreads();
    if (t == 0 && out_size > BATCH * OUTD) {
        float mi = 0.f, ml = 0.f;
        for (int e = 0; e < NEXP; e++) { mi += imp[e]; ml += loadv[e]; }
        mi /= NEXP; ml /= NEXP;
        float vi = 0.f, vl = 0.f;
        for (int e = 0; e < NEXP; e++) {
            float di = imp[e] - mi, dl = loadv[e] - ml;
            vi += di * di; vl += dl * dl;
        }
        vi /= NEXP; vl /= NEXP;
        out[BATCH * OUTD] =
            0.01f * (vi / (mi * mi + 1e-10f) + vl / (ml * ml + 1e-10f));
    }
}

// ------------------------------- launcher ----------------------------------
extern "C" void kernel_launch(void* const* d_in, const int* in_sizes, int n_in,
                              void* d_out, int out_size)
{
    (void)in_sizes; (void)n_in;
    const float* x   = (const float*)d_in[0];
    const float* cw1 = (const float*)d_in[1];
    const float* cb1 = (const float*)d_in[2];
    const float* cw2 = (const float*)d_in[3];
    const float* cb2 = (const float*)d_in[4];
    const float* cw3 = (const float*)d_in[5];
    const float* cb3 = (const float*)d_in[6];
    const float* cw4 = (const float*)d_in[7];
    const float* cb4 = (const float*)d_in[8];
    const float* cw5 = (const float*)d_in[9];
    const float* cb5 = (const float*)d_in[10];
    const float* w1  = (const float*)d_in[11];
    const float* b1  = (const float*)d_in[12];
    const float* w2  = (const float*)d_in[13];
    const float* b2  = (const float*)d_in[14];
    const float* wg  = (const float*)d_in[15];
    float* y = (float*)d_out;

    float *pool_s, *o_s;
    unsigned *pkA, *pkB, *whh, *featpk, *hpk;
    unsigned short *hiA, *hiB, *wlo, *feathi, *hhi;
    cudaGetSymbolAddress((void**)&pool_s, g_pool);
    cudaGetSymbolAddress((void**)&o_s, g_o);
    cudaGetSymbolAddress((void**)&pkA, g_pkA);
    cudaGetSymbolAddress((void**)&pkB, g_pkB);
    cudaGetSymbolAddress((void**)&hiA, g_hiA);
    cudaGetSymbolAddress((void**)&hiB, g_hiB);
    cudaGetSymbolAddress((void**)&whh, g_whh);
    cudaGetSymbolAddress((void**)&wlo, g_wlo);
    cudaGetSymbolAddress((void**)&featpk, g_featpk);
    cudaGetSymbolAddress((void**)&feathi, g_feathi);
    cudaGetSymbolAddress((void**)&hpk, g_hpk);
    cudaGetSymbolAddress((void**)&hhi, g_hhi);

    cudaFuncSetAttribute(conv1_kernel,
                         cudaFuncAttributeMaxDynamicSharedMemorySize, CONV1_DSM);
    cudaFuncSetAttribute(conv_mma_kernel<128, 32, 32, 256, false>,
                         cudaFuncAttributeMaxDynamicSharedMemorySize, CONV_DSM);
    cudaFuncSetAttribute(conv_mma_kernel<256, 16, 16, 256, false>,
                         cudaFuncAttributeMaxDynamicSharedMemorySize, CONV_DSM);
    cudaFuncSetAttribute(conv_mma_kernel<256, 8, 8, 512, false>,
                         cudaFuncAttributeMaxDynamicSharedMemorySize, CONV_DSM);
    cudaFuncSetAttribute(conv_mma_kernel<512, 4, 4, 512, true>,
                         cudaFuncAttributeMaxDynamicSharedMemorySize, CONV_DSM);
    cudaFuncSetAttribute(expert_mma_kernel<DFEAT, HID, true, true, true>,
                         cudaFuncAttributeMaxDynamicSharedMemorySize, EXP_DSM);
    cudaFuncSetAttribute(expert_mma_kernel<HID, OUTD, false, false, false>,
                         cudaFuncAttributeMaxDynamicSharedMemorySize, EXP_DSM);

    // weight offsets within g_whh/g_wlo (elements)
    const size_t OFF2 = 0, OFF3 = 294912, OFF4 = 884736, OFF5 = 2064384;

    // ---- all conv weight packs upfront ----
    wpack_kernel<<<(256 * 128 * 9 + 255) / 256, 256>>>(cw2, whh + OFF2, wlo + OFF2, 256, 128);
    wpack_kernel<<<(256 * 256 * 9 + 255) / 256, 256>>>(cw3, whh + OFF3, wlo + OFF3, 256, 256);
    wpack_kernel<<<(512 * 256 * 9 + 255) / 256, 256>>>(cw4, whh + OFF4, wlo + OFF4, 512, 256);
    wpack_kernel<<<(512 * 512 * 9 + 255) / 256, 256>>>(cw5, whh + OFF5, wlo + OFF5, 512, 512);

    // ---- conv stack ----
    conv1_kernel<<<8192, 256, CONV1_DSM>>>(x, cw1, cb1, pkA, hiA);
    conv_mma_kernel<128, 32, 32, 256, false><<<dim3(2048, 2), 256, CONV_DSM>>>(
        pkA, hiA, whh + OFF2, wlo + OFF2, cb2, pkB, hiB, nullptr);
    conv_mma_kernel<256, 16, 16, 256, false><<<dim3(512, 2), 256, CONV_DSM>>>(
        pkB, hiB, whh + OFF3, wlo + OFF3, cb3, pkA, hiA, nullptr);
    conv_mma_kernel<256, 8, 8, 512, false><<<dim3(128, 4), 256, CONV_DSM>>>(
        pkA, hiA, whh + OFF4, wlo + OFF4, cb4, pkB, hiB, nullptr);
    conv_mma_kernel<512, 4, 4, 512, true><<<dim3(32, 4), 256, CONV_DSM>>>(
        pkB, hiB, whh + OFF5, wlo + OFF5, cb5, featpk, feathi, pool_s);

    // ---- gating ----
    gate_logits_kernel<<<NEXP, 256>>>(pool_s, wg);
    topk_perm_kernel<<<1, 512>>>();

    // ---- sparse expert MLPs (bf16 mma) ----
    expert_mma_kernel<DFEAT, HID, true, true, true>
        <<<dim3(HID / 128, NEXP, 8), 256, EXP_DSM>>>(featpk, feathi, w1, b1,
                                                     hpk, hhi, nullptr);
    expert_mma_kernel<HID, OUTD, false, false, false>
        <<<dim3(OUTD / 128, NEXP, 8), 256, EXP_DSM>>>(hpk, hhi, w2, b2,
                                                      nullptr, nullptr, o_s);

    // ---- combine + aux ----
    zero_kernel<<<(out_size + 255) / 256, 256>>>(y, out_size);
    softmax_combine_kernel<<<NPAIR, 256>>>(y);
    aux_kernel<<<1, 256>>>(y, out_size);
}

// round 6
// speedup vs baseline: 3.3389x; 1.0880x over previous
#include <cuda_runtime.h>
#include <cuda_bf16.h>
#include <math.h>
#include <stdint.h>

// ---------------------------------------------------------------------------
// ToyMoE: conv stack (5x conv3x3+relu+maxpool2) -> top-2 gating (eval)
//         -> sparse top-2 expert MLPs -> softmax -> gated combine + aux loss
// conv2-5 & experts: bf16 mma.sync, 3-term split as 3 real-K passes
// (Ahi*Whi + Alo*Whi + Ahi*Wlo), hi/lo u16 activation planes, fused
// pool/split epilogues. 512-thread conv CTAs (16 warps) for tensor util.
// ---------------------------------------------------------------------------

#define BATCH 256
#define DFEAT 2048
#define HID 4096
#define OUTD 1024
#define NEXP 16
#define NPAIR (BATCH * 2)

typedef unsigned short u16;

template <int X> struct LG { static constexpr int v = 1 + LG<X / 2>::v; };
template <> struct LG<1> { static constexpr int v = 0; };

// ------------------------- scratch (device globals) ------------------------
__device__ u16   g_hiA[(size_t)256 * 1024 * 128];  // hi acts (L1/L3 out)
__device__ u16   g_loA[(size_t)256 * 1024 * 128];  // lo acts
__device__ u16   g_hiB[(size_t)256 * 256 * 256];   // hi acts (L2/L4 out)
__device__ u16   g_loB[(size_t)256 * 256 * 256];
__device__ u16   g_whi[4423680];                   // conv weights hi
__device__ u16   g_wlo[4423680];                   // conv weights lo
__device__ float g_pool[BATCH * DFEAT];            // feats fp32 (gating)
__device__ u16   g_feathi[BATCH * DFEAT];
__device__ u16   g_featlo[BATCH * DFEAT];
__device__ u16   g_hhi[(size_t)NPAIR * HID];
__device__ u16   g_hlo[(size_t)NPAIR * HID];
__device__ float g_logits[BATCH * NEXP];
__device__ float g_gates[BATCH * NEXP];
__device__ int   g_pairE[NPAIR];
__device__ float g_pairG[NPAIR];
__device__ int   g_perm[NPAIR];
__device__ int   g_cnt[NEXP];
__device__ int   g_off[NEXP];
__device__ float g_o[(size_t)NPAIR * OUTD];

// ------------------------------ PTX helpers --------------------------------
__device__ __forceinline__ uint32_t smem_u32(const void* p) {
    uint32_t a;
    asm("{ .reg .u64 t; cvta.to.shared.u64 t, %1; cvt.u32.u64 %0, t; }"
        : "=r"(a) : "l"(p));
    return a;
}

#define SWZ64(x) ((x) ^ (((x) >> 3) & 0x30))

__device__ __forceinline__ void cp16(uint32_t dst, const void* src, int sz) {
    asm volatile("cp.async.cg.shared.global [%0], [%1], 16, %2;"
                 :: "r"(dst), "l"(src), "r"(sz) : "memory");
}
#define CP_COMMIT() asm volatile("cp.async.commit_group;" ::: "memory")
#define CP_WAIT(n)  asm volatile("cp.async.wait_group %0;" :: "n"(n) : "memory")

__device__ __forceinline__ void ldsm4(uint32_t& r0, uint32_t& r1,
                                      uint32_t& r2, uint32_t& r3, uint32_t a) {
    asm volatile("ldmatrix.sync.aligned.m8n8.x4.shared.b16 {%0,%1,%2,%3}, [%4];"
                 : "=r"(r0), "=r"(r1), "=r"(r2), "=r"(r3) : "r"(a));
}
__device__ __forceinline__ void mma16816(float* d, const uint32_t* a,
                                         const uint32_t* b) {
    asm volatile(
        "mma.sync.aligned.m16n8k16.row.col.f32.bf16.bf16.f32 "
        "{%0,%1,%2,%3}, {%4,%5,%6,%7}, {%8,%9}, {%0,%1,%2,%3};"
        : "+f"(d[0]), "+f"(d[1]), "+f"(d[2]), "+f"(d[3])
        : "r"(a[0]), "r"(a[1]), "r"(a[2]), "r"(a[3]), "r"(b[0]), "r"(b[1]));
}
__device__ __forceinline__ void split2(float v, u16* hi, u16* lo) {
    __nv_bfloat16 h = __float2bfloat16_rn(v);
    __nv_bfloat16 l = __float2bfloat16_rn(v - __bfloat162float(h));
    *hi = __bfloat16_as_ushort(h);
    *lo = __bfloat16_as_ushort(l);
}

// --------------------- bf16 mma.sync conv3x3 (SAME, relu, fused pool) ------
// 3 real-K passes per 32-channel tap chunk: Ahi*Whi + Alo*Whi + Ahi*Wlo.
// Stage 32KB = Ahi(8K) Alo(8K) Whi(8K) Wlo(8K), all SW64. 3 stages, 1 sync.
#define STG 32768
#define CONV_DSM (3 * STG)

template <int CI, int H, int W, int CO, bool FEATS>
__global__ void __launch_bounds__(512, 1) conv_mma_kernel(
    const u16* __restrict__ inhi, const u16* __restrict__ inlo,
    const u16* __restrict__ whi, const u16* __restrict__ wlo,
    const float* __restrict__ bias,
    u16* __restrict__ outhi, u16* __restrict__ outlo, float* __restrict__ outf)
{
    constexpr int HW = H * W;
    constexpr int LHW = LG<HW>::v;
    constexpr int LW = LG<W>::v;
    constexpr int CPT = CI / 32;
    constexpr int NCH = 9 * CPT;
    constexpr int WROW = 9 * CI;

    extern __shared__ __align__(1024) char dsm[];
    const uint32_t sb = smem_u32(dsm);
    const int t = threadIdx.x;
    const int lane = t & 31;
    const int wid = t >> 5;
    const int wm = wid & 3, wn = wid >> 2;     // 4x4 warp grid, 32x32 tiles
    const int m0 = blockIdx.x * 128, n0 = blockIdx.y * 128;

    // fill metadata: one 64B row per thread (r = t>>2, seg = t&3)
    const int r = t >> 2, sg = t & 3;
    const int m = m0 + r;
    const int bI = m >> LHW;
    const int pos = m & (HW - 1);
    const int yy = pos >> LW, xx = pos & (W - 1);
    const size_t wro = (size_t)(n0 + r) * WROW + sg * 8;
    const uint32_t dstA = SWZ64((uint32_t)(r * 64 + sg * 16));

    auto fill = [&](int st, int c) {
        const uint32_t stg = sb + (uint32_t)st * STG;
        const int tap = c / CPT;
        const int cib = (c % CPT) * 32;
        const int dy = tap / 3 - 1, dx = tap % 3 - 1;
        const int iy = yy + dy, ix = xx + dx;
        const bool ok = (iy >= 0 && iy < H && ix >= 0 && ix < W);
        const size_t ai =
            (((size_t)bI * H + (ok ? iy : 0)) * W + (ok ? ix : 0)) * CI + cib + sg * 8;
        cp16(stg + dstA, inhi + ai, ok ? 16 : 0);
        cp16(stg + 8192 + dstA, inlo + ai, ok ? 16 : 0);
        const size_t wi = wro + tap * CI + cib;
        cp16(stg + 16384 + dstA, whi + wi, 16);
        cp16(stg + 24576 + dstA, wlo + wi, 16);
    };

    float acc[2][4][4];
#pragma unroll
    for (int a = 0; a < 2; a++)
#pragma unroll
        for (int b = 0; b < 4; b++)
#pragma unroll
            for (int cj = 0; cj < 4; cj++) acc[a][b][cj] = 0.f;

    fill(0, 0);
    CP_COMMIT();
    fill(1, 1);
    CP_COMMIT();

    int st = 0;
    for (int c = 0; c < NCH; c++) {
        if (c + 1 < NCH) { CP_WAIT(1); } else { CP_WAIT(0); }
        __syncthreads();
        if (c + 2 < NCH) {
            fill(st >= 1 ? st - 1 : st + 2, c + 2);
            CP_COMMIT();
        }
        const uint32_t stg = sb + (uint32_t)st * STG;
#pragma unroll
        for (int ks = 0; ks < 2; ks++) {
            const int c0 = ks * 32;
            uint32_t ah[2][4], al[2][4], bh[8], bl[8];
#pragma unroll
            for (int mt = 0; mt < 2; mt++) {
                const int row = wm * 32 + mt * 16 + (lane & 15);
                const uint32_t off = SWZ64((uint32_t)(row * 64 + c0 + (lane >> 4) * 16));
                ldsm4(ah[mt][0], ah[mt][1], ah[mt][2], ah[mt][3], stg + off);
                ldsm4(al[mt][0], al[mt][1], al[mt][2], al[mt][3], stg + 8192 + off);
            }
#pragma unroll
            for (int p = 0; p < 2; p++) {
                const int row = wn * 32 + p * 16 + (lane & 7) + (lane >> 4) * 8;
                const uint32_t off =
                    SWZ64((uint32_t)(row * 64 + c0 + ((lane >> 3) & 1) * 16));
                ldsm4(bh[p * 4], bh[p * 4 + 1], bh[p * 4 + 2], bh[p * 4 + 3],
                      stg + 16384 + off);
                ldsm4(bl[p * 4], bl[p * 4 + 1], bl[p * 4 + 2], bl[p * 4 + 3],
                      stg + 24576 + off);
            }
#pragma unroll
            for (int mt = 0; mt < 2; mt++)
#pragma unroll
                for (int nt = 0; nt < 4; nt++) {
                    mma16816(acc[mt][nt], ah[mt], &bh[nt * 2]);
                    mma16816(acc[mt][nt], al[mt], &bh[nt * 2]);
                    mma16816(acc[mt][nt], ah[mt], &bl[nt * 2]);
                }
        }
        st = (st + 1 == 3) ? 0 : st + 1;
    }
    __syncthreads();

    // ---- epilogue: bias+relu -> SMEM tile -> 2x2 pool -> hi/lo planes ----
    float* S = (float*)dsm;  // [128][132]
#pragma unroll
    for (int mt = 0; mt < 2; mt++)
#pragma unroll
        for (int half = 0; half < 2; half++) {
            const int rr = wm * 32 + mt * 16 + (lane >> 2) + half * 8;
#pragma unroll
            for (int nt = 0; nt < 4; nt++)
#pragma unroll
                for (int j = 0; j < 2; j++) {
                    const int ncl = wn * 32 + nt * 8 + (lane & 3) * 2 + j;
                    float v = acc[mt][nt][half * 2 + j] + bias[n0 + ncl];
                    S[rr * 132 + ncl] = v > 0.f ? v : 0.f;
                }
        }
    __syncthreads();

    constexpr int Wo = W / 2;
    constexpr int HWo = HW / 4;
    for (int idx = t; idx < 32 * 128; idx += 512) {
        const int pp = idx >> 7;
        const int cl = idx & 127;
        const int lpy = pp / Wo;
        const int lpx = pp % Wo;
        const int lm = lpy * 2 * W + lpx * 2;
        const int mm = m0 + lm;
        const int b = mm >> LHW;
        const int rem = mm & (HW - 1);
        const int y = rem >> LW, x = rem & (W - 1);
        const float* p = S + lm * 132 + cl;
        float v = fmaxf(fmaxf(p[0], p[132]), fmaxf(p[W * 132], p[(W + 1) * 132]));
        const int posn = (y >> 1) * Wo + (x >> 1);
        u16 hb, lb;
        split2(v, &hb, &lb);
        if (FEATS) {
            const int d = (n0 + cl) * HWo + posn;
            outf[(size_t)b * DFEAT + d] = v;
            outhi[(size_t)b * DFEAT + d] = hb;
            outlo[(size_t)b * DFEAT + d] = lb;
        } else {
            const size_t oi = ((size_t)b * HWo + posn) * CO + (n0 + cl);
            outhi[oi] = hb;
            outlo[oi] = lb;
        }
    }
}

// ---- weight pack: OIHW -> [co][tap*CI+ci] hi u16 / lo u16 -----------------
__global__ void wpack_kernel(const float* __restrict__ w,
                             u16* __restrict__ ohi, u16* __restrict__ olo,
                             int CO, int CI)
{
    const int i = blockIdx.x * 256 + threadIdx.x;
    if (i >= CO * CI * 9) return;
    const int tap = i % 9;
    const int ci = (i / 9) % CI;
    const int co = i / (9 * CI);
    u16 hb, lb;
    split2(w[i], &hb, &lb);
    const size_t o = (size_t)co * CI * 9 + (size_t)tap * CI + ci;
    ohi[o] = hb;
    olo[o] = lb;
}

// -------------- grouped expert GEMM, bf16 mma (fc1 / fc2) ------------------
// M-tile 32 x N-tile 128, chunk = 32 k. W fp32 converted in-kernel to SW64
// hi/lo. Stage 36KB, 3 stages, 2 CTAs/SM.
#define ESTG 36864
#define EXP_DSM (3 * ESTG + 128)

template <int KDIM, int NDIM, bool RELU, bool GATHER, bool PACKOUT>
__global__ void __launch_bounds__(256, 2) expert_mma_kernel(
    const u16* __restrict__ Ahi, const u16* __restrict__ Alo,
    const float* __restrict__ Wt, const float* __restrict__ bias,
    u16* __restrict__ ohp, u16* __restrict__ olp, float* __restrict__ of)
{
    constexpr int NCH = KDIM / 32;
    const int e = blockIdx.y;
    const int cnt = g_cnt[e];
    const int off = g_off[e];
    const int rbase = blockIdx.z * 32;
    if (rbase >= cnt) return;
    const int n0 = blockIdx.x * 128;

    extern __shared__ __align__(1024) char dsm[];
    const uint32_t sb = smem_u32(dsm);
    const int t = threadIdx.x;
    const int lane = t & 31;
    const int wn = t >> 5;

    int* srcRow = (int*)(dsm + 3 * ESTG);
    if (t < 32) {
        int rr = rbase + t, sr = -1;
        if (rr < cnt) sr = GATHER ? (g_perm[off + rr] >> 1) : (off + rr);
        srcRow[t] = sr;
    }
    __syncthreads();

    const float* wbase = Wt + (size_t)e * KDIM * NDIM + n0;

    auto fill = [&](int st, int c) {
        const uint32_t stg = sb + (uint32_t)st * ESTG;
        const int kb = c * 32;
        if (t < 128) {
            const int rr = t >> 2, sg = t & 3;
            const int sr = srcRow[rr];
            const size_t ai = (sr < 0) ? 0 : ((size_t)sr * KDIM + kb + sg * 8);
            const uint32_t d = SWZ64((uint32_t)(rr * 64 + sg * 16));
            cp16(stg + d, Ahi + ai, sr < 0 ? 0 : 16);
            cp16(stg + 2048 + d, Alo + ai, sr < 0 ? 0 : 16);
        }
#pragma unroll
        for (int i = 0; i < 4; i++) {
            const int task = t + i * 256;
            const int k = task >> 5, sgw = task & 31;
            cp16(stg + 4096 + (uint32_t)(k * 512 + sgw * 16),
                 wbase + (size_t)(kb + k) * NDIM + sgw * 4, 16);
        }
    };

    float acc[2][2][4];
#pragma unroll
    for (int a = 0; a < 2; a++)
#pragma unroll
        for (int b = 0; b < 2; b++)
#pragma unroll
            for (int cj = 0; cj < 4; cj++) acc[a][b][cj] = 0.f;

    fill(0, 0);
    CP_COMMIT();
    fill(1, 1);
    CP_COMMIT();

    int st = 0;
    for (int c = 0; c < NCH; c++) {
        if (c + 1 < NCH) { CP_WAIT(1); } else { CP_WAIT(0); }
        __syncthreads();
        if (c + 2 < NCH) {
            fill(st >= 1 ? st - 1 : st + 2, c + 2);
            CP_COMMIT();
        }
        char* stgc = dsm + (size_t)st * ESTG;
        // ---- convert W fp32 tile -> Whi / Wlo (SW64, n-major) ----
        {
            const int k = t >> 3, ng = t & 7;
#pragma unroll
            for (int j = 0; j < 4; j++) {
                const float4 w =
                    *(const float4*)(stgc + 4096 + k * 512 + ng * 64 + j * 16);
                const float vv[4] = {w.x, w.y, w.z, w.w};
#pragma unroll
                for (int jj = 0; jj < 4; jj++) {
                    const int n = ng * 16 + j * 4 + jj;
                    u16 hb, lb;
                    split2(vv[jj], &hb, &lb);
                    const uint32_t o = SWZ64((uint32_t)(n * 64 + 2 * k));
                    *(u16*)(stgc + 20480 + o) = hb;
                    *(u16*)(stgc + 28672 + o) = lb;
                }
            }
        }
        __syncthreads();

        const uint32_t stg = sb + (uint32_t)st * ESTG;
#pragma unroll
        for (int ks = 0; ks < 2; ks++) {
            const int c0 = ks * 32;
            uint32_t ah[2][4], al[2][4], bh[4], bl[4];
#pragma unroll
            for (int mt = 0; mt < 2; mt++) {
                const int row = mt * 16 + (lane & 15);
                const uint32_t o = SWZ64((uint32_t)(row * 64 + c0 + (lane >> 4) * 16));
                ldsm4(ah[mt][0], ah[mt][1], ah[mt][2], ah[mt][3], stg + o);
                ldsm4(al[mt][0], al[mt][1], al[mt][2], al[mt][3], stg + 2048 + o);
            }
            {
                const int row = wn * 16 + (lane & 7) + (lane >> 4) * 8;
                const uint32_t o =
                    SWZ64((uint32_t)(row * 64 + c0 + ((lane >> 3) & 1) * 16));
                ldsm4(bh[0], bh[1], bh[2], bh[3], stg + 20480 + o);
                ldsm4(bl[0], bl[1], bl[2], bl[3], stg + 28672 + o);
            }
#pragma unroll
            for (int mt = 0; mt < 2; mt++)
#pragma unroll
                for (int nt = 0; nt < 2; nt++) {
                    mma16816(acc[mt][nt], ah[mt], &bh[nt * 2]);
                    mma16816(acc[mt][nt], al[mt], &bh[nt * 2]);
                    mma16816(acc[mt][nt], ah[mt], &bl[nt * 2]);
                }
        }
        st = (st + 1 == 3) ? 0 : st + 1;
    }

    // ---- epilogue ----
#pragma unroll
    for (int mt = 0; mt < 2; mt++)
#pragma unroll
        for (int half = 0; half < 2; half++) {
            const int rr = rbase + mt * 16 + (lane >> 2) + half * 8;
            if (rr >= cnt) continue;
            const int gr = off + rr;
#pragma unroll
            for (int nt = 0; nt < 2; nt++)
#pragma unroll
                for (int j = 0; j < 2; j++) {
                    const int n = n0 + wn * 16 + nt * 8 + (lane & 3) * 2 + j;
                    float v = acc[mt][nt][half * 2 + j] + bias[(size_t)e * NDIM + n];
                    if (RELU) v = v > 0.f ? v : 0.f;
                    if (PACKOUT) {
                        u16 hb, lb;
                        split2(v, &hb, &lb);
                        ohp[(size_t)gr * NDIM + n] = hb;
                        olp[(size_t)gr * NDIM + n] = lb;
                    } else {
                        of[(size_t)gr * NDIM + n] = v;
                    }
                }
        }
}

// ---------- conv1: fp32 SIMT (CI=3) with fused pool+split epilogue ---------
#define CONV1_DSM 68608

__global__ __launch_bounds__(256, 1) void conv1_kernel(
    const float* __restrict__ in, const float* __restrict__ wt,
    const float* __restrict__ bias, u16* __restrict__ outhi,
    u16* __restrict__ outlo)
{
    constexpr int CI = 3, H = 64, W = 64;
    constexpr int BK = 27;
    constexpr int HW = H * W;

    extern __shared__ __align__(1024) char dsm[];
    float (*As)[132] = (float(*)[132])dsm;
    float (*Bs)[132] = (float(*)[132])(dsm + 14784);

    const int t = threadIdx.x;
    const int m0 = blockIdx.x * 128;
    const int tx = t & 15;
    const int ty = t >> 4;

    float acc[8][8];
#pragma unroll
    for (int i = 0; i < 8; i++)
#pragma unroll
        for (int j = 0; j < 8; j++) acc[i][j] = 0.f;

#pragma unroll
    for (int j = 0; j < 14; j++) {
        int e = j * 256 + t;
        if (e >= 27 * 128) break;
        int k = e >> 7;
        int p = e & 127;
        int ci = k / 9;
        int rc = k % 9;
        int s = m0 + p;
        int b = s / HW;
        int rr = s % HW;
        int y = rr / W, x = rr % W;
        int iy = y + rc / 3 - 1;
        int ix = x + rc % 3 - 1;
        float v = 0.f;
        if (iy >= 0 && iy < H && ix >= 0 && ix < W)
            v = in[((size_t)(b * CI + ci) * H + iy) * W + ix];
        As[k][p] = v;
    }
    if (t < 128) {
        const float* wp = wt + (size_t)t * 27;
#pragma unroll
        for (int k = 0; k < 27; k++) Bs[k][t] = wp[k];
    }
    __syncthreads();

#pragma unroll
    for (int kk = 0; kk < BK; kk++) {
        float a[8], bv[8];
        *(float4*)&a[0] = *(const float4*)&As[kk][tx * 8];
        *(float4*)&a[4] = *(const float4*)&As[kk][tx * 8 + 4];
        *(float4*)&bv[0] = *(const float4*)&Bs[kk][ty * 8];
        *(float4*)&bv[4] = *(const float4*)&Bs[kk][ty * 8 + 4];
#pragma unroll
        for (int i = 0; i < 8; i++)
#pragma unroll
            for (int j = 0; j < 8; j++) acc[i][j] += a[i] * bv[j];
    }
    __syncthreads();

    float* S = (float*)dsm;
#pragma unroll
    for (int i = 0; i < 8; i++) {
        const int r = tx * 8 + i;
#pragma unroll
        for (int j = 0; j < 8; j++) {
            const int cl = ty * 8 + j;
            float v = acc[i][j] + bias[cl];
            S[r * 132 + cl] = v > 0.f ? v : 0.f;
        }
    }
    __syncthreads();

    for (int idx = t; idx < 32 * 128; idx += 256) {
        const int pp = idx >> 7;
        const int cl = idx & 127;
        const int lm = pp * 2;
        const int m = m0 + lm;
        const int b = m >> 12;
        const int rem = m & 4095;
        const int y = rem >> 6, x = rem & 63;
        const float* p = S + lm * 132 + cl;
        float v = fmaxf(fmaxf(p[0], p[132]), fmaxf(p[64 * 132], p[65 * 132]));
        u16 hb, lb;
        split2(v, &hb, &lb);
        const size_t oi = ((size_t)b * 1024 + (y >> 1) * 32 + (x >> 1)) * 128 + cl;
        outhi[oi] = hb;
        outlo[oi] = lb;
    }
}

// ----------------------------- gate logits ---------------------------------
__global__ void gate_logits_kernel(const float* __restrict__ feats,
                                   const float* __restrict__ wg)
{
    int t = blockIdx.x * blockDim.x + threadIdx.x;
    if (t >= BATCH * NEXP) return;
    int b = t >> 4, e = t & 15;
    const float* f = feats + (size_t)b * DFEAT;
    float s = 0.f;
    for (int d = 0; d < DFEAT; d++) s += f[d] * wg[d * NEXP + e];
    g_logits[t] = s;
}

// ------------------- top-2 + gate softmax + perm (fused) -------------------
__global__ void topk_perm_kernel()
{
    __shared__ int scnt[NEXP], soff[NEXP], scur[NEXP];
    const int t = threadIdx.x;  // 512
    if (t < BATCH) {
        const int b = t;
        float l[NEXP];
#pragma unroll
        for (int e = 0; e < NEXP; e++) l[e] = g_logits[b * NEXP + e];
        float b1v = -INFINITY, b2v = -INFINITY;
        int b1i = 0, b2i = 0;
#pragma unroll
        for (int e = 0; e < NEXP; e++) {
            float v = l[e];
            if (v > b1v) { b2v = b1v; b2i = b1i; b1v = v; b1i = e; }
            else if (v > b2v) { b2v = v; b2i = e; }
        }
        float e2 = expf(b2v - b1v);
        float denom = 1.f + e2;
        float gate1 = 1.f / denom;
        float gate2 = e2 / denom;
#pragma unroll
        for (int e = 0; e < NEXP; e++) g_gates[b * NEXP + e] = 0.f;
        g_gates[b * NEXP + b1i] = gate1;
        g_gates[b * NEXP + b2i] = gate2;
        g_pairE[2 * b] = b1i;     g_pairG[2 * b] = gate1;
        g_pairE[2 * b + 1] = b2i; g_pairG[2 * b + 1] = gate2;
    }
    if (t < NEXP) { scnt[t] = 0; scur[t] = 0; }
    __syncthreads();
    const int e = g_pairE[t];
    atomicAdd(&scnt[e], 1);
    __syncthreads();
    if (t == 0) {
        int o = 0;
        for (int i = 0; i < NEXP; i++) { soff[i] = o; o += scnt[i]; }
    }
    __syncthreads();
    const int slot = soff[e] + atomicAdd(&scur[e], 1);
    g_perm[slot] = t;
    if (t < NEXP) { g_cnt[t] = scnt[t]; g_off[t] = soff[t]; }
}

// -------------------------- zero output buffer -----------------------------
__global__ void zero_kernel(float* __restrict__ p, int n)
{
    int i = blockIdx.x * blockDim.x + threadIdx.x;
    if (i < n) p[i] = 0.f;
}

// ------------------- softmax over experts' logits + combine ----------------
__global__ void softmax_combine_kernel(float* __restrict__ y)
{
    const int gr = blockIdx.x;
    const int t = threadIdx.x;
    const int pair = g_perm[gr];
    const int token = pair >> 1;
    const float gate = g_pairG[pair];
    const float* row = g_o + (size_t)gr * OUTD;

    __shared__ float red[256];
    float m = -INFINITY;
    for (int j = t; j < OUTD; j += 256) m = fmaxf(m, row[j]);
    red[t] = m;
    __syncthreads();
    for (int s = 128; s > 0; s >>= 1) {
        if (t < s) red[t] = fmaxf(red[t], red[t + s]);
        __syncthreads();
    }
    const float M = red[0];
    __syncthreads();

    float s = 0.f;
    for (int j = t; j < OUTD; j += 256) s += expf(row[j] - M);
    red[t] = s;
    __syncthreads();
    for (int st = 128; st > 0; st >>= 1) {
        if (t < st) red[t] += red[t + st];
        __syncthreads();
    }
    const float scale = gate / red[0];

    for (int j = t; j < OUTD; j += 256)
        atomicAdd(&y[(size_t)token * OUTD + j], expf(row[j] - M) * scale);
}

// ------------------------------- aux loss ----------------------------------
__global__ void aux_kernel(float* __restrict__ out, int out_size)
{
    __shared__ float imp[NEXP], loadv[NEXP];
    int t = threadIdx.x;
    if (t < NEXP) {
        float s = 0.f, L = 0.f;
        for (int b = 0; b < BATCH; b++) {
            float gv = g_gates[b * NEXP + t];
            s += gv;
            if (gv > 0.f) L += 1.f;
        }
        imp[t] = s;
        loadv[t] = L;
    }
    __syncthreads();
    if (t == 0 && out_size > BATCH * OUTD) {
        float mi = 0.f, ml = 0.f;
        for (int e = 0; e < NEXP; e++) { mi += imp[e]; ml += loadv[e]; }
        mi /= NEXP; ml /= NEXP;
        float vi = 0.f, vl = 0.f;
        for (int e = 0; e < NEXP; e++) {
            float di = imp[e] - mi, dl = loadv[e] - ml;
            vi += di * di; vl += dl * dl;
        }
        vi /= NEXP; vl /= NEXP;
        out[BATCH * OUTD] =
            0.01f * (vi / (mi * mi + 1e-10f) + vl / (ml * ml + 1e-10f));
    }
}

// ------------------------------- launcher ----------------------------------
extern "C" void kernel_launch(void* const* d_in, const int* in_sizes, int n_in,
                              void* d_out, int out_size)
{
    (void)in_sizes; (void)n_in;
    const float* x   = (const float*)d_in[0];
    const float* cw1 = (const float*)d_in[1];
    const float* cb1 = (const float*)d_in[2];
    const float* cw2 = (const float*)d_in[3];
    const float* cb2 = (const float*)d_in[4];
    const float* cw3 = (const float*)d_in[5];
    const float* cb3 = (const float*)d_in[6];
    const float* cw4 = (const float*)d_in[7];
    const float* cb4 = (const float*)d_in[8];
    const float* cw5 = (const float*)d_in[9];
    const float* cb5 = (const float*)d_in[10];
    const float* w1  = (const float*)d_in[11];
    const float* b1  = (const float*)d_in[12];
    const float* w2  = (const float*)d_in[13];
    const float* b2  = (const float*)d_in[14];
    const float* wg  = (const float*)d_in[15];
    float* y = (float*)d_out;

    float *pool_s, *o_s;
    u16 *hiA, *loA, *hiB, *loB, *whi, *wlo, *feathi, *featlo, *hhi, *hlo;
    cudaGetSymbolAddress((void**)&pool_s, g_pool);
    cudaGetSymbolAddress((void**)&o_s, g_o);
    cudaGetSymbolAddress((void**)&hiA, g_hiA);
    cudaGetSymbolAddress((void**)&loA, g_loA);
    cudaGetSymbolAddress((void**)&hiB, g_hiB);
    cudaGetSymbolAddress((void**)&loB, g_loB);
    cudaGetSymbolAddress((void**)&whi, g_whi);
    cudaGetSymbolAddress((void**)&wlo, g_wlo);
    cudaGetSymbolAddress((void**)&feathi, g_feathi);
    cudaGetSymbolAddress((void**)&featlo, g_featlo);
    cudaGetSymbolAddress((void**)&hhi, g_hhi);
    cudaGetSymbolAddress((void**)&hlo, g_hlo);

    cudaFuncSetAttribute(conv1_kernel,
                         cudaFuncAttributeMaxDynamicSharedMemorySize, CONV1_DSM);
    cudaFuncSetAttribute(conv_mma_kernel<128, 32, 32, 256, false>,
                         cudaFuncAttributeMaxDynamicSharedMemorySize, CONV_DSM);
    cudaFuncSetAttribute(conv_mma_kernel<256, 16, 16, 256, false>,
                         cudaFuncAttributeMaxDynamicSharedMemorySize, CONV_DSM);
    cudaFuncSetAttribute(conv_mma_kernel<256, 8, 8, 512, false>,
                         cudaFuncAttributeMaxDynamicSharedMemorySize, CONV_DSM);
    cudaFuncSetAttribute(conv_mma_kernel<512, 4, 4, 512, true>,
                         cudaFuncAttributeMaxDynamicSharedMemorySize, CONV_DSM);
    cudaFuncSetAttribute(expert_mma_kernel<DFEAT, HID, true, true, true>,
                         cudaFuncAttributeMaxDynamicSharedMemorySize, EXP_DSM);
    cudaFuncSetAttribute(expert_mma_kernel<HID, OUTD, false, false, false>,
                         cudaFuncAttributeMaxDynamicSharedMemorySize, EXP_DSM);

    // weight offsets within g_whi/g_wlo (elements)
    const size_t OFF2 = 0, OFF3 = 294912, OFF4 = 884736, OFF5 = 2064384;

    // ---- all conv weight packs upfront ----
    wpack_kernel<<<(256 * 128 * 9 + 255) / 256, 256>>>(cw2, whi + OFF2, wlo + OFF2, 256, 128);
    wpack_kernel<<<(256 * 256 * 9 + 255) / 256, 256>>>(cw3, whi + OFF3, wlo + OFF3, 256, 256);
    wpack_kernel<<<(512 * 256 * 9 + 255) / 256, 256>>>(cw4, whi + OFF4, wlo + OFF4, 512, 256);
    wpack_kernel<<<(512 * 512 * 9 + 255) / 256, 256>>>(cw5, whi + OFF5, wlo + OFF5, 512, 512);

    // ---- conv stack ----
    conv1_kernel<<<8192, 256, CONV1_DSM>>>(x, cw1, cb1, hiA, loA);
    conv_mma_kernel<128, 32, 32, 256, false><<<dim3(2048, 2), 512, CONV_DSM>>>(
        hiA, loA, whi + OFF2, wlo + OFF2, cb2, hiB, loB, nullptr);
    conv_mma_kernel<256, 16, 16, 256, false><<<dim3(512, 2), 512, CONV_DSM>>>(
        hiB, loB, whi + OFF3, wlo + OFF3, cb3, hiA, loA, nullptr);
    conv_mma_kernel<256, 8, 8, 512, false><<<dim3(128, 4), 512, CONV_DSM>>>(
        hiA, loA, whi + OFF4, wlo + OFF4, cb4, hiB, loB, nullptr);
    conv_mma_kernel<512, 4, 4, 512, true><<<dim3(32, 4), 512, CONV_DSM>>>(
        hiB, loB, whi + OFF5, wlo + OFF5, cb5, feathi, featlo, pool_s);

    // ---- gating ----
    gate_logits_kernel<<<NEXP, 256>>>(pool_s, wg);
    topk_perm_kernel<<<1, 512>>>();

    // ---- sparse expert MLPs (bf16 mma) ----
    expert_mma_kernel<DFEAT, HID, true, true, true>
        <<<dim3(HID / 128, NEXP, 8), 256, EXP_DSM>>>(feathi, featlo, w1, b1,
                                                     hhi, hlo, nullptr);
    expert_mma_kernel<HID, OUTD, false, false, false>
        <<<dim3(OUTD / 128, NEXP, 8), 256, EXP_DSM>>>(hhi, hlo, w2, b2,
                                                      nullptr, nullptr, o_s);

    // ---- combine + aux ----
    zero_kernel<<<(out_size + 255) / 256, 256>>>(y, out_size);
    softmax_combine_kernel<<<NPAIR, 256>>>(y);
    aux_kernel<<<1, 256>>>(y, out_size);
}